// round 12
// baseline (speedup 1.0000x reference)
#include <cuda_runtime.h>
#include <math.h>

#define BB 4
#define NN 4096
#define CC 256
#define NQ 14
#define DK 512
#define NM 15

// ---------------- scratch (device globals; allocation-free) ----------------
__device__ float g_qs[BB*NN*CC];
__device__ float g_kk[BB*NN*CC];
__device__ float g_vv[BB*NN*CC];
__device__ float g_kh[BB*NN*DK];
__device__ float g_vh[BB*NN*DK];
__device__ float g_seed[BB*NQ*CC];
__device__ float g_qh[BB*NQ*DK];
__device__ float g_logits[BB*NQ*NN];
__device__ float g_ctx[BB*NQ*DK];
__device__ float g_pkn[BB*NQ*CC];
__device__ float g_pqn[BB*NQ*CC];
__device__ float g_q2p[BB*NN*NQ];
__device__ int   g_sidq[BB*NN];
__device__ float g_Kmat[BB*NN*NM];
__device__ float g_s2p[BB*NN*NQ];
__device__ int   g_sids[BB*NN];
__device__ float g_rowm[BB*NM];
__device__ float g_Ptab[NQ*NQ];
__device__ float g_part[2*8*NM];
__device__ int   g_ctr;
__device__ float g_xattn[BB*NN*CC];

__device__ __forceinline__ float d4(float4 a, float4 b) {
    return a.x*b.x + a.y*b.y + a.z*b.z + a.w*b.w;
}
__device__ __forceinline__ float wsum(float v) {
    #pragma unroll
    for (int o = 16; o; o >>= 1) v += __shfl_xor_sync(0xffffffffu, v, o);
    return v;
}
__device__ __forceinline__ float wmax(float v) {
    #pragma unroll
    for (int o = 16; o; o >>= 1) v = fmaxf(v, __shfl_xor_sync(0xffffffffu, v, o));
    return v;
}

// ---------------------------------------------------------------------------
// GEMM, K=256: Y[16384, NC] = X[16384,256] @ W[256,NC].  128x128 tile, 8x8 micro.
// ---------------------------------------------------------------------------
__global__ __launch_bounds__(256) void gemm_k256(const float* __restrict__ X,
                                                 const float* __restrict__ W,
                                                 float* __restrict__ Y, int NC)
{
    __shared__ __align__(16) float Xs[16][128];
    __shared__ __align__(16) float Bs[16][128];
    const int t  = threadIdx.x;
    const int m0 = blockIdx.y * 128;
    const int n0 = blockIdx.x * 128;
    const int tx = t & 15, ty = t >> 4;

    float acc[8][8];
    #pragma unroll
    for (int i = 0; i < 8; i++)
        #pragma unroll
        for (int j = 0; j < 8; j++) acc[i][j] = 0.f;

    for (int kt = 0; kt < 256; kt += 16) {
        __syncthreads();
        #pragma unroll
        for (int h = 0; h < 2; h++) {
            int f4  = t + 256 * h;
            int row = f4 >> 2, kq = f4 & 3;
            float4 xv = *(const float4*)(X + (size_t)(m0 + row) * 256 + kt + kq * 4);
            Xs[kq*4+0][row] = xv.x; Xs[kq*4+1][row] = xv.y;
            Xs[kq*4+2][row] = xv.z; Xs[kq*4+3][row] = xv.w;
            int r = f4 >> 5, c4 = f4 & 31;
            *(float4*)&Bs[r][c4*4] = *(const float4*)(W + (size_t)(kt + r) * NC + n0 + c4 * 4);
        }
        __syncthreads();
        #pragma unroll
        for (int kk2 = 0; kk2 < 16; kk2++) {
            float4 a0 = *(float4*)&Xs[kk2][ty*8];
            float4 a1 = *(float4*)&Xs[kk2][ty*8+4];
            float4 b0 = *(float4*)&Bs[kk2][tx*8];
            float4 b1 = *(float4*)&Bs[kk2][tx*8+4];
            float av[8] = {a0.x,a0.y,a0.z,a0.w,a1.x,a1.y,a1.z,a1.w};
            float bv[8] = {b0.x,b0.y,b0.z,b0.w,b1.x,b1.y,b1.z,b1.w};
            #pragma unroll
            for (int i = 0; i < 8; i++)
                #pragma unroll
                for (int j = 0; j < 8; j++) acc[i][j] += av[i] * bv[j];
        }
    }
    #pragma unroll
    for (int i = 0; i < 8; i++) {
        float* yr = Y + (size_t)(m0 + ty*8 + i) * NC + n0 + tx*8;
        *(float4*)yr       = make_float4(acc[i][0], acc[i][1], acc[i][2], acc[i][3]);
        *(float4*)(yr + 4) = make_float4(acc[i][4], acc[i][5], acc[i][6], acc[i][7]);
    }
}

// ---------------------------------------------------------------------------
// Prep: alignment table, row marginals, barrier counter reset
// ---------------------------------------------------------------------------
__global__ __launch_bounds__(256) void prep_kernel(const int* __restrict__ supp_mask)
{
    int t = threadIdx.x;
    if (t == 0) g_ctr = 0;
    if (t < NQ*NQ) {
        int s = t / NQ, q = t % NQ;
        int prod = (2*s + 3) * (2*q + 3);
        int r = (int)(sqrtf((float)prod) + 0.5f);
        g_Ptab[t] = (r*r == prod) ? 0.f : -10000.f;
    }
    __shared__ int red[256];
    int b = t >> 6, j = t & 63;
    int cnt = 0;
    for (int i = j; i < NN; i += 64) cnt += (supp_mask[b*NN + i] == 0);
    red[t] = cnt;
    __syncthreads();
    for (int o = 32; o; o >>= 1) { if (j < o) red[t] += red[t + o]; __syncthreads(); }
    if (j == 0) {
        float nbg = (float)red[t];
        float nfg = (float)NN - nbg;
        for (int m2 = 0; m2 < NQ; m2++) g_rowm[b*NM + m2] = nfg / (float)(NQ * NN);
        g_rowm[b*NM + NQ] = nbg / (float)NN;
    }
}

// ---------------------------------------------------------------------------
// seed[b,q,d] = sum_c sv[b,c,q]*Ws[c,d];  qh = seed @ Wqs
// ---------------------------------------------------------------------------
__global__ __launch_bounds__(256) void seed_qh_kernel(const float* __restrict__ sv,
                                                      const float* __restrict__ Ws,
                                                      const float* __restrict__ Wqs)
{
    __shared__ float svc[CC];
    __shared__ float sd[CC];
    int bq = blockIdx.x;
    int b = bq / NQ, q = bq % NQ;
    int t = threadIdx.x;
    svc[t] = sv[((size_t)b*CC + t)*NQ + q];
    __syncthreads();
    float a = 0.f;
    #pragma unroll 8
    for (int c = 0; c < CC; c++) a += svc[c] * Ws[(size_t)c*CC + t];
    g_seed[(size_t)bq*CC + t] = a;
    sd[t] = a;
    __syncthreads();
    #pragma unroll
    for (int h = 0; h < 2; h++) {
        int d = t + 256*h;
        float a2 = 0.f;
        #pragma unroll 8
        for (int c = 0; c < CC; c++) a2 += sd[c] * Wqs[(size_t)c*DK + d];
        g_qh[(size_t)bq*DK + d] = a2;
    }
}

// ---------------------------------------------------------------------------
// logits[b,q,n] = qh.kh/sqrt(512), masked -1e9 where supp_mask==0
// ---------------------------------------------------------------------------
__global__ __launch_bounds__(256) void logits_kernel(const int* __restrict__ supp_mask)
{
    __shared__ __align__(16) float qh_s[NQ*DK];
    int b = blockIdx.y;
    int n = blockIdx.x * 256 + threadIdx.x;
    for (int i = threadIdx.x; i < NQ*DK; i += 256) qh_s[i] = g_qh[(size_t)b*NQ*DK + i];
    __syncthreads();
    const float4* kh4 = (const float4*)(g_kh + ((size_t)b*NN + n) * DK);
    float acc[NQ];
    #pragma unroll
    for (int q = 0; q < NQ; q++) acc[q] = 0.f;
    for (int c4 = 0; c4 < DK/4; c4++) {
        float4 kv = kh4[c4];
        #pragma unroll
        for (int q = 0; q < NQ; q++) {
            float4 qv = *(float4*)&qh_s[q*DK + c4*4];
            acc[q] += d4(kv, qv);
        }
    }
    const float sc = 0.044194173824159216f;  // 1/sqrt(512)
    bool masked = (supp_mask[b*NN + n] == 0);
    #pragma unroll
    for (int q = 0; q < NQ; q++)
        g_logits[((size_t)b*NQ + q)*NN + n] = masked ? -1e9f : acc[q] * sc;
}

// ---------------------------------------------------------------------------
// A = softmax(logits); ctx[b,q,d] = sum_n A[n]*vh[b,n,d]   (one block per (q,b))
// ---------------------------------------------------------------------------
__global__ __launch_bounds__(512) void softmax_ctx_kernel()
{
    __shared__ float ls[NN];
    __shared__ float red[512];
    int q = blockIdx.x, b = blockIdx.y, t = threadIdx.x;
    const float* lrow = g_logits + ((size_t)b*NQ + q) * NN;
    float lmax = -INFINITY;
    for (int i = t; i < NN; i += 512) { float v = lrow[i]; ls[i] = v; lmax = fmaxf(lmax, v); }
    red[t] = lmax;
    __syncthreads();
    for (int o = 256; o; o >>= 1) { if (t < o) red[t] = fmaxf(red[t], red[t+o]); __syncthreads(); }
    float m = red[0];
    __syncthreads();
    float lsum = 0.f;
    for (int i = t; i < NN; i += 512) { float p = expf(ls[i] - m); ls[i] = p; lsum += p; }
    red[t] = lsum;
    __syncthreads();
    for (int o = 256; o; o >>= 1) { if (t < o) red[t] += red[t+o]; __syncthreads(); }
    float S = red[0];
    __syncthreads();
    const float* vb = g_vh + (size_t)b*NN*DK;
    float a0 = 0.f, a1 = 0.f, a2 = 0.f, a3 = 0.f;
    for (int n = 0; n < NN; n += 4) {
        a0 += ls[n+0] * vb[(size_t)(n+0)*DK + t];
        a1 += ls[n+1] * vb[(size_t)(n+1)*DK + t];
        a2 += ls[n+2] * vb[(size_t)(n+2)*DK + t];
        a3 += ls[n+3] * vb[(size_t)(n+3)*DK + t];
    }
    g_ctx[((size_t)b*NQ + q)*DK + t] = ((a0 + a1) + (a2 + a3)) / S;
}

// ---------------------------------------------------------------------------
// prototypes = LN(ctx@Wfc + bfc + seed); pk=prot@Wsk, pq=prot@Wsq, l2-normalized
// ---------------------------------------------------------------------------
__global__ __launch_bounds__(256) void proto_kernel(const float* __restrict__ Wfc,
    const float* __restrict__ bfc, const float* __restrict__ ln_g,
    const float* __restrict__ ln_b, const float* __restrict__ Wsk,
    const float* __restrict__ Wsq)
{
    __shared__ float cs[DK];
    __shared__ float ps[CC];
    __shared__ float red[256];
    int bq = blockIdx.x, t = threadIdx.x;
    cs[t]       = g_ctx[(size_t)bq*DK + t];
    cs[t + 256] = g_ctx[(size_t)bq*DK + t + 256];
    __syncthreads();
    float pre = bfc[t] + g_seed[(size_t)bq*CC + t];
    #pragma unroll 8
    for (int k2 = 0; k2 < DK; k2++) pre += cs[k2] * Wfc[(size_t)k2*CC + t];
    red[t] = pre;
    __syncthreads();
    for (int o = 128; o; o >>= 1) { if (t < o) red[t] += red[t+o]; __syncthreads(); }
    float mu = red[0] * (1.f/256.f);
    __syncthreads();
    float dd = pre - mu;
    red[t] = dd * dd;
    __syncthreads();
    for (int o = 128; o; o >>= 1) { if (t < o) red[t] += red[t+o]; __syncthreads(); }
    float var = red[0] * (1.f/256.f);
    __syncthreads();
    float prot = dd / sqrtf(var + 1e-5f) * ln_g[t] + ln_b[t];
    ps[t] = prot;
    __syncthreads();
    float pk = 0.f, pq = 0.f;
    #pragma unroll 8
    for (int c = 0; c < CC; c++) {
        float pv = ps[c];
        pk += pv * Wsk[(size_t)c*CC + t];
        pq += pv * Wsq[(size_t)c*CC + t];
    }
    red[t] = pk * pk;
    __syncthreads();
    for (int o = 128; o; o >>= 1) { if (t < o) red[t] += red[t+o]; __syncthreads(); }
    float nk = sqrtf(red[0]);
    __syncthreads();
    red[t] = pq * pq;
    __syncthreads();
    for (int o = 128; o; o >>= 1) { if (t < o) red[t] += red[t+o]; __syncthreads(); }
    float nq2 = sqrtf(red[0]);
    g_pkn[(size_t)bq*CC + t] = pk / fmaxf(nk,  1e-12f);
    g_pqn[(size_t)bq*CC + t] = pq / fmaxf(nq2, 1e-12f);
}

// ---------------------------------------------------------------------------
// Per-row: q2p (+argmax), Kmat = exp(-cost/0.05). One warp per row.
// ---------------------------------------------------------------------------
__global__ __launch_bounds__(256) void rowsim_kernel(const int* __restrict__ supp_mask)
{
    __shared__ __align__(16) float pkn_s[NQ*CC];
    __shared__ __align__(16) float pqn_s[NQ*CC];
    int t = threadIdx.x, lane = t & 31, wid = t >> 5;
    int g = blockIdx.x * 8 + wid;
    int b = g >> 12;
    for (int i = t; i < NQ*CC; i += 256) {
        pkn_s[i] = g_pkn[(size_t)b*NQ*CC + i];
        pqn_s[i] = g_pqn[(size_t)b*NQ*CC + i];
    }
    __syncthreads();
    const float* qrow = g_qs + (size_t)g*CC;
    const float* krow = g_kk + (size_t)g*CC;
    float4 q0 = *(const float4*)(qrow + lane*4);
    float4 q1 = *(const float4*)(qrow + 128 + lane*4);
    float4 k0 = *(const float4*)(krow + lane*4);
    float4 k1 = *(const float4*)(krow + 128 + lane*4);
    float rnq = 1.f / fmaxf(sqrtf(wsum(d4(q0,q0) + d4(q1,q1))), 1e-12f);
    float rnk = 1.f / fmaxf(sqrtf(wsum(d4(k0,k0) + d4(k1,k1))), 1e-12f);
    float myq2p = 0.f, myK = 0.f;
    float best = -INFINITY; int bk = 0;
    #pragma unroll
    for (int k2 = 0; k2 < NQ; k2++) {
        float4 p0 = *(float4*)&pkn_s[k2*CC + lane*4];
        float4 p1 = *(float4*)&pkn_s[k2*CC + 128 + lane*4];
        float val = wsum(d4(q0,p0) + d4(q1,p1)) * rnq;
        if (val > best) { best = val; bk = k2; }
        if (lane == k2) myq2p = val;
        float4 r0 = *(float4*)&pqn_s[k2*CC + lane*4];
        float4 r1 = *(float4*)&pqn_s[k2*CC + 128 + lane*4];
        float a = wsum(d4(k0,r0) + d4(k1,r1)) * rnk;
        if (lane == k2) myK = expf(20.f * (a - 1.f));   // exp(-(1-att)/0.05)
    }
    if (lane < NQ) {
        g_q2p[(size_t)g*NQ + lane]  = myq2p;
        g_Kmat[(size_t)g*NM + lane] = myK;
    }
    if (lane == NQ)
        g_Kmat[(size_t)g*NM + NQ] = (supp_mask[g] > 0) ? expf(-40.f) : 1.f;
    if (lane == 0) g_sidq[g] = bk;
}

// ---------------------------------------------------------------------------
// Sinkhorn: 8 blocks (2 per batch), K in registers, 100 iterations with a
// parity-buffered global-counter barrier. Fixed-order sums -> deterministic.
// ---------------------------------------------------------------------------
__global__ __launch_bounds__(512) void sinkhorn_kernel()
{
    __shared__ float sred[16*NM];
    __shared__ float v_s[NM];
    int t = threadIdx.x, lane = t & 31, wid = t >> 5;
    int b = blockIdx.x >> 1, half = blockIdx.x & 1;

    float Kl[4][NM];
    int rowg[4];
    #pragma unroll
    for (int i = 0; i < 4; i++) {
        int n = half*2048 + i*512 + t;
        rowg[i] = b*NN + n;
        #pragma unroll
        for (int j = 0; j < NM; j++) Kl[i][j] = g_Kmat[(size_t)rowg[i]*NM + j];
    }
    float u[4] = {1.f/NN, 1.f/NN, 1.f/NN, 1.f/NN};

    for (int iter = 0; iter < 100; iter++) {
        #pragma unroll
        for (int j = 0; j < NM; j++) {
            float x = Kl[0][j]*u[0] + Kl[1][j]*u[1] + Kl[2][j]*u[2] + Kl[3][j]*u[3];
            x = wsum(x);
            if (lane == 0) sred[wid*NM + j] = x;
        }
        __syncthreads();
        if (t < NM) {
            float bp = 0.f;
            for (int w = 0; w < 16; w++) bp += sred[w*NM + t];
            g_part[((iter & 1)*8 + blockIdx.x)*NM + t] = bp;
            __threadfence();
        }
        __syncthreads();
        if (t == 0) {
            atomicAdd(&g_ctr, 1);
            while (atomicAdd(&g_ctr, 0) < 8*(iter + 1)) { }
            __threadfence();
        }
        __syncthreads();
        if (t < NM) {
            volatile float* vp = (volatile float*)g_part;
            int base = ((iter & 1)*8 + b*2)*NM;
            float tot = vp[base + t] + vp[base + NM + t];
            v_s[t] = g_rowm[b*NM + t] / (tot + 1e-16f);
        }
        __syncthreads();
        #pragma unroll
        for (int i = 0; i < 4; i++) {
            float dsum = 0.f;
            #pragma unroll
            for (int j = 0; j < NM; j++) dsum += Kl[i][j]*v_s[j];
            u[i] = (1.f/NN) / (dsum + 1e-16f);
        }
    }
    #pragma unroll
    for (int i = 0; i < 4; i++) {
        float best = -INFINITY; int bk = 0;
        #pragma unroll
        for (int j = 0; j < NQ; j++) {
            float tv = fmaxf(u[i]*Kl[i][j]*v_s[j]*(float)NN, 0.f);
            g_s2p[(size_t)rowg[i]*NQ + j] = tv;
            if (tv > best) { best = tv; bk = j; }
        }
        g_sids[rowg[i]] = bk;
    }
}

// ---------------------------------------------------------------------------
// Flash: x[b,i,:] = softmax_j(q2p[i].s2p[j] - 1e4*valid[j] - 1e4*notalign) @ vv
// 8 warps x 4 rows per block; 32-key tiles; vv tile in smem.
// ---------------------------------------------------------------------------
__global__ __launch_bounds__(256) void flash_kernel(const int* __restrict__ valid)
{
    __shared__ __align__(16) float vvs[32][256];
    __shared__ float s2ps[32][NQ];
    __shared__ float q2ps[32][NQ];
    __shared__ float vmask[32];
    __shared__ int   sidss[32];
    __shared__ int   sidqs[32];
    __shared__ float ptab[NQ*NQ];
    int t = threadIdx.x, lane = t & 31, wid = t >> 5;
    int b  = blockIdx.y;
    int i0 = blockIdx.x * 32;

    for (int i = t; i < NQ*NQ; i += 256) ptab[i] = g_Ptab[i];
    for (int i = t; i < 32*NQ; i += 256) q2ps[i/NQ][i%NQ] = g_q2p[((size_t)b*NN + i0)*NQ + i];
    if (t < 32) sidqs[t] = g_sidq[b*NN + i0 + t];

    const int r0 = wid * 4;
    float m[4]  = {-INFINITY, -INFINITY, -INFINITY, -INFINITY};
    float l[4]  = {0.f, 0.f, 0.f, 0.f};
    float acc[4][8];
    #pragma unroll
    for (int r = 0; r < 4; r++)
        #pragma unroll
        for (int i = 0; i < 8; i++) acc[r][i] = 0.f;

    for (int kt = 0; kt < NN/32; kt++) {
        int k0 = kt * 32;
        __syncthreads();
        for (int i = t; i < 32*NQ; i += 256) s2ps[i/NQ][i%NQ] = g_s2p[((size_t)b*NN + k0)*NQ + i];
        if (t < 32) {
            vmask[t] = -10000.f * (float)valid[b*NN + k0 + t];
            sidss[t] = g_sids[b*NN + k0 + t];
        }
        #pragma unroll
        for (int h = 0; h < 8; h++) {
            int f4 = t + 256*h;
            int row = f4 >> 6, c4 = f4 & 63;
            *(float4*)&vvs[row][c4*4] =
                *(const float4*)(g_vv + ((size_t)b*NN + k0 + row)*CC + c4*4);
        }
        __syncthreads();

        float sc[4];
        #pragma unroll
        for (int r = 0; r < 4; r++) {
            float x = vmask[lane] + ptab[sidqs[r0+r]*NQ + sidss[lane]];
            #pragma unroll
            for (int k2 = 0; k2 < NQ; k2++) x += q2ps[r0+r][k2] * s2ps[lane][k2];
            sc[r] = x;
        }
        #pragma unroll
        for (int r = 0; r < 4; r++) {
            float mn = fmaxf(m[r], wmax(sc[r]));
            float scale = expf(m[r] - mn);
            m[r] = mn;
            float p = expf(sc[r] - mn);
            sc[r] = p;
            l[r] = l[r]*scale + wsum(p);
            #pragma unroll
            for (int i = 0; i < 8; i++) acc[r][i] *= scale;
        }
        #pragma unroll
        for (int j = 0; j < 32; j++) {
            float p0 = __shfl_sync(0xffffffffu, sc[0], j);
            float p1 = __shfl_sync(0xffffffffu, sc[1], j);
            float p2 = __shfl_sync(0xffffffffu, sc[2], j);
            float p3 = __shfl_sync(0xffffffffu, sc[3], j);
            #pragma unroll
            for (int i = 0; i < 8; i++) {
                float vvv = vvs[j][lane + 32*i];
                acc[0][i] += p0 * vvv;
                acc[1][i] += p1 * vvv;
                acc[2][i] += p2 * vvv;
                acc[3][i] += p3 * vvv;
            }
        }
    }
    #pragma unroll
    for (int r = 0; r < 4; r++) {
        float inv = 1.f / l[r];
        size_t base = ((size_t)b*NN + i0 + r0 + r)*CC;
        #pragma unroll
        for (int i = 0; i < 8; i++)
            g_xattn[base + lane + 32*i] = acc[r][i] * inv;
    }
}

// ---------------------------------------------------------------------------
// Launch
// ---------------------------------------------------------------------------
extern "C" void kernel_launch(void* const* d_in, const int* in_sizes, int n_in,
                              void* d_out, int out_size)
{
    (void)in_sizes; (void)n_in; (void)out_size;
    const float* q      = (const float*)d_in[0];
    const float* k      = (const float*)d_in[1];
    const float* v      = (const float*)d_in[2];
    const float* sv     = (const float*)d_in[3];
    const int*   svalid = (const int*)d_in[4];
    const int*   smask  = (const int*)d_in[5];
    const float* Wq     = (const float*)d_in[6];
    const float* Wk     = (const float*)d_in[7];
    const float* Wv     = (const float*)d_in[8];
    const float* Ws     = (const float*)d_in[9];
    const float* Wsq    = (const float*)d_in[10];
    const float* Wsk    = (const float*)d_in[11];
    const float* Wproj  = (const float*)d_in[12];
    const float* Wqs    = (const float*)d_in[13];
    const float* Wks    = (const float*)d_in[14];
    const float* Wvs    = (const float*)d_in[15];
    const float* Wfc    = (const float*)d_in[16];
    const float* bfc    = (const float*)d_in[17];
    const float* lng    = (const float*)d_in[18];
    const float* lnb    = (const float*)d_in[19];
    float* out = (float*)d_out;

    float *p_qs, *p_kk, *p_vv, *p_kh, *p_vh, *p_xa;
    cudaGetSymbolAddress((void**)&p_qs, g_qs);
    cudaGetSymbolAddress((void**)&p_kk, g_kk);
    cudaGetSymbolAddress((void**)&p_vv, g_vv);
    cudaGetSymbolAddress((void**)&p_kh, g_kh);
    cudaGetSymbolAddress((void**)&p_vh, g_vh);
    cudaGetSymbolAddress((void**)&p_xa, g_xattn);

    dim3 g256(2, 128), g512(4, 128);
    prep_kernel<<<1, 256>>>(smask);
    gemm_k256<<<g256, 256>>>(q, Wq, p_qs, 256);
    gemm_k256<<<g256, 256>>>(k, Wk, p_kk, 256);
    gemm_k256<<<g256, 256>>>(v, Wv, p_vv, 256);
    seed_qh_kernel<<<BB*NQ, 256>>>(sv, Ws, Wqs);
    gemm_k256<<<g512, 256>>>(p_kk, Wks, p_kh, 512);
    gemm_k256<<<g512, 256>>>(p_vv, Wvs, p_vh, 512);
    logits_kernel<<<dim3(NN/256, BB), 256>>>(smask);
    softmax_ctx_kernel<<<dim3(NQ, BB), 512>>>();
    proto_kernel<<<BB*NQ, 256>>>(Wfc, bfc, lng, lnb, Wsk, Wsq);
    rowsim_kernel<<<BB*NN/8, 256>>>(smask);
    sinkhorn_kernel<<<8, 512>>>();
    flash_kernel<<<dim3(NN/32, BB), 256>>>(svalid);
    gemm_k256<<<g256, 256>>>(p_xa, Wproj, out, 256);
}

// round 13
// speedup vs baseline: 1.3838x; 1.3838x over previous
#include <cuda_runtime.h>
#include <math.h>

#define BB 4
#define NN 4096
#define CC 256
#define NQ 14
#define DK 512
#define NM 15

// ---------------- scratch (device globals; allocation-free) ----------------
__device__ float g_qs[BB*NN*CC];
__device__ float g_kk[BB*NN*CC];
__device__ float g_vv[BB*NN*CC];
__device__ float g_kh[BB*NN*DK];
__device__ float g_vh[BB*NN*DK];
__device__ float g_seed[BB*NQ*CC];
__device__ float g_qh[BB*NQ*DK];
__device__ float g_logits[BB*NQ*NN];
__device__ float g_ctx[BB*NQ*DK];
__device__ float g_pkn[BB*NQ*CC];
__device__ float g_pqn[BB*NQ*CC];
__device__ float g_q2p[BB*NN*NQ];
__device__ int   g_sidq[BB*NN];
__device__ float g_Kmat[BB*NN*NM];
__device__ float g_s2p[BB*NN*NQ];
__device__ int   g_sids[BB*NN];
__device__ float g_rowm[BB*NM];
__device__ float g_Ptab[NQ*NQ];
__device__ float g_part[2*8*NM];
__device__ int   g_ctr;
__device__ float g_xattn[BB*NN*CC];

__device__ __forceinline__ float d4(float4 a, float4 b) {
    return a.x*b.x + a.y*b.y + a.z*b.z + a.w*b.w;
}
__device__ __forceinline__ float wsum(float v) {
    #pragma unroll
    for (int o = 16; o; o >>= 1) v += __shfl_xor_sync(0xffffffffu, v, o);
    return v;
}
__device__ __forceinline__ unsigned tf32r(float x) {
    unsigned y; asm("cvt.rna.tf32.f32 %0, %1;" : "=r"(y) : "f"(x)); return y;
}
__device__ __forceinline__ void mma8(float& d0, float& d1, float& d2, float& d3,
    unsigned a0, unsigned a1, unsigned a2, unsigned a3, unsigned b0, unsigned b1)
{
    asm volatile("mma.sync.aligned.m16n8k8.row.col.f32.tf32.tf32.f32 "
        "{%0,%1,%2,%3},{%4,%5,%6,%7},{%8,%9},{%0,%1,%2,%3};"
        : "+f"(d0), "+f"(d1), "+f"(d2), "+f"(d3)
        : "r"(a0), "r"(a1), "r"(a2), "r"(a3), "r"(b0), "r"(b1));
}

// ---------------------------------------------------------------------------
// GEMM, K=256: Y[16384, NC] = X[16384,256] @ W[256,NC].  128x128 tile, 8x8 micro.
// ---------------------------------------------------------------------------
__global__ __launch_bounds__(256) void gemm_k256(const float* __restrict__ X,
                                                 const float* __restrict__ W,
                                                 float* __restrict__ Y, int NC)
{
    __shared__ __align__(16) float Xs[16][128];
    __shared__ __align__(16) float Bs[16][128];
    const int t  = threadIdx.x;
    const int m0 = blockIdx.y * 128;
    const int n0 = blockIdx.x * 128;
    const int tx = t & 15, ty = t >> 4;

    float acc[8][8];
    #pragma unroll
    for (int i = 0; i < 8; i++)
        #pragma unroll
        for (int j = 0; j < 8; j++) acc[i][j] = 0.f;

    for (int kt = 0; kt < 256; kt += 16) {
        __syncthreads();
        #pragma unroll
        for (int h = 0; h < 2; h++) {
            int f4  = t + 256 * h;
            int row = f4 >> 2, kq = f4 & 3;
            float4 xv = *(const float4*)(X + (size_t)(m0 + row) * 256 + kt + kq * 4);
            Xs[kq*4+0][row] = xv.x; Xs[kq*4+1][row] = xv.y;
            Xs[kq*4+2][row] = xv.z; Xs[kq*4+3][row] = xv.w;
            int r = f4 >> 5, c4 = f4 & 31;
            *(float4*)&Bs[r][c4*4] = *(const float4*)(W + (size_t)(kt + r) * NC + n0 + c4 * 4);
        }
        __syncthreads();
        #pragma unroll
        for (int kk2 = 0; kk2 < 16; kk2++) {
            float4 a0 = *(float4*)&Xs[kk2][ty*8];
            float4 a1 = *(float4*)&Xs[kk2][ty*8+4];
            float4 b0 = *(float4*)&Bs[kk2][tx*8];
            float4 b1 = *(float4*)&Bs[kk2][tx*8+4];
            float av[8] = {a0.x,a0.y,a0.z,a0.w,a1.x,a1.y,a1.z,a1.w};
            float bv[8] = {b0.x,b0.y,b0.z,b0.w,b1.x,b1.y,b1.z,b1.w};
            #pragma unroll
            for (int i = 0; i < 8; i++)
                #pragma unroll
                for (int j = 0; j < 8; j++) acc[i][j] += av[i] * bv[j];
        }
    }
    #pragma unroll
    for (int i = 0; i < 8; i++) {
        float* yr = Y + (size_t)(m0 + ty*8 + i) * NC + n0 + tx*8;
        *(float4*)yr       = make_float4(acc[i][0], acc[i][1], acc[i][2], acc[i][3]);
        *(float4*)(yr + 4) = make_float4(acc[i][4], acc[i][5], acc[i][6], acc[i][7]);
    }
}

// ---------------------------------------------------------------------------
// Prep: alignment table, row marginals, barrier counter reset
// ---------------------------------------------------------------------------
__global__ __launch_bounds__(256) void prep_kernel(const int* __restrict__ supp_mask)
{
    int t = threadIdx.x;
    if (t == 0) g_ctr = 0;
    if (t < NQ*NQ) {
        int s = t / NQ, q = t % NQ;
        int prod = (2*s + 3) * (2*q + 3);
        int r = (int)(sqrtf((float)prod) + 0.5f);
        g_Ptab[t] = (r*r == prod) ? 0.f : -10000.f;
    }
    __shared__ int red[256];
    int b = t >> 6, j = t & 63;
    int cnt = 0;
    for (int i = j; i < NN; i += 64) cnt += (supp_mask[b*NN + i] == 0);
    red[t] = cnt;
    __syncthreads();
    for (int o = 32; o; o >>= 1) { if (j < o) red[t] += red[t + o]; __syncthreads(); }
    if (j == 0) {
        float nbg = (float)red[t];
        float nfg = (float)NN - nbg;
        for (int m2 = 0; m2 < NQ; m2++) g_rowm[b*NM + m2] = nfg / (float)(NQ * NN);
        g_rowm[b*NM + NQ] = nbg / (float)NN;
    }
}

// ---------------------------------------------------------------------------
// seed[b,q,d] = sum_c sv[b,c,q]*Ws[c,d];  qh = seed @ Wqs
// ---------------------------------------------------------------------------
__global__ __launch_bounds__(256) void seed_qh_kernel(const float* __restrict__ sv,
                                                      const float* __restrict__ Ws,
                                                      const float* __restrict__ Wqs)
{
    __shared__ float svc[CC];
    __shared__ float sd[CC];
    int bq = blockIdx.x;
    int b = bq / NQ, q = bq % NQ;
    int t = threadIdx.x;
    svc[t] = sv[((size_t)b*CC + t)*NQ + q];
    __syncthreads();
    float a = 0.f;
    #pragma unroll 8
    for (int c = 0; c < CC; c++) a += svc[c] * Ws[(size_t)c*CC + t];
    g_seed[(size_t)bq*CC + t] = a;
    sd[t] = a;
    __syncthreads();
    #pragma unroll
    for (int h = 0; h < 2; h++) {
        int d = t + 256*h;
        float a2 = 0.f;
        #pragma unroll 8
        for (int c = 0; c < CC; c++) a2 += sd[c] * Wqs[(size_t)c*DK + d];
        g_qh[(size_t)bq*DK + d] = a2;
    }
}

// ---------------------------------------------------------------------------
// logits[b,q,n] = qh.kh/sqrt(512), masked -1e9 where supp_mask==0
// ---------------------------------------------------------------------------
__global__ __launch_bounds__(256) void logits_kernel(const int* __restrict__ supp_mask)
{
    __shared__ __align__(16) float qh_s[NQ*DK];
    int b = blockIdx.y;
    int n = blockIdx.x * 256 + threadIdx.x;
    for (int i = threadIdx.x; i < NQ*DK; i += 256) qh_s[i] = g_qh[(size_t)b*NQ*DK + i];
    __syncthreads();
    const float4* kh4 = (const float4*)(g_kh + ((size_t)b*NN + n) * DK);
    float acc[NQ];
    #pragma unroll
    for (int q = 0; q < NQ; q++) acc[q] = 0.f;
    for (int c4 = 0; c4 < DK/4; c4++) {
        float4 kv = kh4[c4];
        #pragma unroll
        for (int q = 0; q < NQ; q++) {
            float4 qv = *(float4*)&qh_s[q*DK + c4*4];
            acc[q] += d4(kv, qv);
        }
    }
    const float sc = 0.044194173824159216f;  // 1/sqrt(512)
    bool masked = (supp_mask[b*NN + n] == 0);
    #pragma unroll
    for (int q = 0; q < NQ; q++)
        g_logits[((size_t)b*NQ + q)*NN + n] = masked ? -1e9f : acc[q] * sc;
}

// ---------------------------------------------------------------------------
// A = softmax(logits); ctx[b,q,d] = sum_n A[n]*vh[b,n,d]
// ---------------------------------------------------------------------------
__global__ __launch_bounds__(512) void softmax_ctx_kernel()
{
    __shared__ float ls[NN];
    __shared__ float red[512];
    int q = blockIdx.x, b = blockIdx.y, t = threadIdx.x;
    const float* lrow = g_logits + ((size_t)b*NQ + q) * NN;
    float lmax = -INFINITY;
    for (int i = t; i < NN; i += 512) { float v = lrow[i]; ls[i] = v; lmax = fmaxf(lmax, v); }
    red[t] = lmax;
    __syncthreads();
    for (int o = 256; o; o >>= 1) { if (t < o) red[t] = fmaxf(red[t], red[t+o]); __syncthreads(); }
    float m = red[0];
    __syncthreads();
    float lsum = 0.f;
    for (int i = t; i < NN; i += 512) { float p = expf(ls[i] - m); ls[i] = p; lsum += p; }
    red[t] = lsum;
    __syncthreads();
    for (int o = 256; o; o >>= 1) { if (t < o) red[t] += red[t+o]; __syncthreads(); }
    float S = red[0];
    __syncthreads();
    const float* vb = g_vh + (size_t)b*NN*DK;
    float a0 = 0.f, a1 = 0.f, a2 = 0.f, a3 = 0.f;
    for (int n = 0; n < NN; n += 4) {
        a0 += ls[n+0] * vb[(size_t)(n+0)*DK + t];
        a1 += ls[n+1] * vb[(size_t)(n+1)*DK + t];
        a2 += ls[n+2] * vb[(size_t)(n+2)*DK + t];
        a3 += ls[n+3] * vb[(size_t)(n+3)*DK + t];
    }
    g_ctx[((size_t)b*NQ + q)*DK + t] = ((a0 + a1) + (a2 + a3)) / S;
}

// ---------------------------------------------------------------------------
// prototypes = LN(ctx@Wfc + bfc + seed); pk/pq l2-normalized
// ---------------------------------------------------------------------------
__global__ __launch_bounds__(256) void proto_kernel(const float* __restrict__ Wfc,
    const float* __restrict__ bfc, const float* __restrict__ ln_g,
    const float* __restrict__ ln_b, const float* __restrict__ Wsk,
    const float* __restrict__ Wsq)
{
    __shared__ float cs[DK];
    __shared__ float ps[CC];
    __shared__ float red[256];
    int bq = blockIdx.x, t = threadIdx.x;
    cs[t]       = g_ctx[(size_t)bq*DK + t];
    cs[t + 256] = g_ctx[(size_t)bq*DK + t + 256];
    __syncthreads();
    float pre = bfc[t] + g_seed[(size_t)bq*CC + t];
    #pragma unroll 8
    for (int k2 = 0; k2 < DK; k2++) pre += cs[k2] * Wfc[(size_t)k2*CC + t];
    red[t] = pre;
    __syncthreads();
    for (int o = 128; o; o >>= 1) { if (t < o) red[t] += red[t+o]; __syncthreads(); }
    float mu = red[0] * (1.f/256.f);
    __syncthreads();
    float dd = pre - mu;
    red[t] = dd * dd;
    __syncthreads();
    for (int o = 128; o; o >>= 1) { if (t < o) red[t] += red[t+o]; __syncthreads(); }
    float var = red[0] * (1.f/256.f);
    __syncthreads();
    float prot = dd / sqrtf(var + 1e-5f) * ln_g[t] + ln_b[t];
    ps[t] = prot;
    __syncthreads();
    float pk = 0.f, pq = 0.f;
    #pragma unroll 8
    for (int c = 0; c < CC; c++) {
        float pv = ps[c];
        pk += pv * Wsk[(size_t)c*CC + t];
        pq += pv * Wsq[(size_t)c*CC + t];
    }
    red[t] = pk * pk;
    __syncthreads();
    for (int o = 128; o; o >>= 1) { if (t < o) red[t] += red[t+o]; __syncthreads(); }
    float nk = sqrtf(red[0]);
    __syncthreads();
    red[t] = pq * pq;
    __syncthreads();
    for (int o = 128; o; o >>= 1) { if (t < o) red[t] += red[t+o]; __syncthreads(); }
    float nq2 = sqrtf(red[0]);
    g_pkn[(size_t)bq*CC + t] = pk / fmaxf(nk,  1e-12f);
    g_pqn[(size_t)bq*CC + t] = pq / fmaxf(nq2, 1e-12f);
}

// ---------------------------------------------------------------------------
// Per-row: q2p (+argmax), Kmat = exp(-cost/0.05). One warp per row.
// ---------------------------------------------------------------------------
__global__ __launch_bounds__(256) void rowsim_kernel(const int* __restrict__ supp_mask)
{
    __shared__ __align__(16) float pkn_s[NQ*CC];
    __shared__ __align__(16) float pqn_s[NQ*CC];
    int t = threadIdx.x, lane = t & 31, wid = t >> 5;
    int g = blockIdx.x * 8 + wid;
    int b = g >> 12;
    for (int i = t; i < NQ*CC; i += 256) {
        pkn_s[i] = g_pkn[(size_t)b*NQ*CC + i];
        pqn_s[i] = g_pqn[(size_t)b*NQ*CC + i];
    }
    __syncthreads();
    const float* qrow = g_qs + (size_t)g*CC;
    const float* krow = g_kk + (size_t)g*CC;
    float4 q0 = *(const float4*)(qrow + lane*4);
    float4 q1 = *(const float4*)(qrow + 128 + lane*4);
    float4 k0 = *(const float4*)(krow + lane*4);
    float4 k1 = *(const float4*)(krow + 128 + lane*4);
    float rnq = 1.f / fmaxf(sqrtf(wsum(d4(q0,q0) + d4(q1,q1))), 1e-12f);
    float rnk = 1.f / fmaxf(sqrtf(wsum(d4(k0,k0) + d4(k1,k1))), 1e-12f);
    float myq2p = 0.f, myK = 0.f;
    float best = -INFINITY; int bk = 0;
    #pragma unroll
    for (int k2 = 0; k2 < NQ; k2++) {
        float4 p0 = *(float4*)&pkn_s[k2*CC + lane*4];
        float4 p1 = *(float4*)&pkn_s[k2*CC + 128 + lane*4];
        float val = wsum(d4(q0,p0) + d4(q1,p1)) * rnq;
        if (val > best) { best = val; bk = k2; }
        if (lane == k2) myq2p = val;
        float4 r0 = *(float4*)&pqn_s[k2*CC + lane*4];
        float4 r1 = *(float4*)&pqn_s[k2*CC + 128 + lane*4];
        float a = wsum(d4(k0,r0) + d4(k1,r1)) * rnk;
        if (lane == k2) myK = expf(20.f * (a - 1.f));
    }
    if (lane < NQ) {
        g_q2p[(size_t)g*NQ + lane]  = myq2p;
        g_Kmat[(size_t)g*NM + lane] = myK;
    }
    if (lane == NQ)
        g_Kmat[(size_t)g*NM + NQ] = (supp_mask[g] > 0) ? expf(-40.f) : 1.f;
    if (lane == 0) g_sidq[g] = bk;
}

// ---------------------------------------------------------------------------
// Sinkhorn: 8 blocks (2 per batch), K in registers, global-counter barrier.
// ---------------------------------------------------------------------------
__global__ __launch_bounds__(512) void sinkhorn_kernel()
{
    __shared__ float sred[16*NM];
    __shared__ float v_s[NM];
    int t = threadIdx.x, lane = t & 31, wid = t >> 5;
    int b = blockIdx.x >> 1, half = blockIdx.x & 1;

    float Kl[4][NM];
    int rowg[4];
    #pragma unroll
    for (int i = 0; i < 4; i++) {
        int n = half*2048 + i*512 + t;
        rowg[i] = b*NN + n;
        #pragma unroll
        for (int j = 0; j < NM; j++) Kl[i][j] = g_Kmat[(size_t)rowg[i]*NM + j];
    }
    float u[4] = {1.f/NN, 1.f/NN, 1.f/NN, 1.f/NN};

    for (int iter = 0; iter < 100; iter++) {
        #pragma unroll
        for (int j = 0; j < NM; j++) {
            float x = Kl[0][j]*u[0] + Kl[1][j]*u[1] + Kl[2][j]*u[2] + Kl[3][j]*u[3];
            x = wsum(x);
            if (lane == 0) sred[wid*NM + j] = x;
        }
        __syncthreads();
        if (t < NM) {
            float bp = 0.f;
            for (int w = 0; w < 16; w++) bp += sred[w*NM + t];
            g_part[((iter & 1)*8 + blockIdx.x)*NM + t] = bp;
            __threadfence();
        }
        __syncthreads();
        if (t == 0) {
            atomicAdd(&g_ctr, 1);
            while (atomicAdd(&g_ctr, 0) < 8*(iter + 1)) { }
            __threadfence();
        }
        __syncthreads();
        if (t < NM) {
            volatile float* vp = (volatile float*)g_part;
            int base = ((iter & 1)*8 + b*2)*NM;
            float tot = vp[base + t] + vp[base + NM + t];
            v_s[t] = g_rowm[b*NM + t] / (tot + 1e-16f);
        }
        __syncthreads();
        #pragma unroll
        for (int i = 0; i < 4; i++) {
            float dsum = 0.f;
            #pragma unroll
            for (int j = 0; j < NM; j++) dsum += Kl[i][j]*v_s[j];
            u[i] = (1.f/NN) / (dsum + 1e-16f);
        }
    }
    #pragma unroll
    for (int i = 0; i < 4; i++) {
        float best = -INFINITY; int bk = 0;
        #pragma unroll
        for (int j = 0; j < NQ; j++) {
            float tv = fmaxf(u[i]*Kl[i][j]*v_s[j]*(float)NN, 0.f);
            g_s2p[(size_t)rowg[i]*NQ + j] = tv;
            if (tv > best) { best = tv; bk = j; }
        }
        g_sids[rowg[i]] = bk;
    }
}

// ---------------------------------------------------------------------------
// Flash attention via tf32 mma.m16n8k8. Scores = Qext(32) . Kext(32)^T with
// masks folded in; P stays in registers (C-frag -> A-frag shuffle); PV HMMA
// on a stride-136 V tile (conflict-free). 128 q-rows x 128 cols per block.
// ---------------------------------------------------------------------------
__global__ __launch_bounds__(256, 2) void flash_mma(const int* __restrict__ valid)
{
    __shared__ uint4 Qf[8*4*32];      // [warp][ks][lane] A-frags of Qext
    __shared__ uint2 Kf[4*4*32];      // [nb][ks][lane]   B-frags of Kext
    __shared__ float Vs[32][136];     // V tile, stride 136 (bank-safe)

    const int t = threadIdx.x, lane = t & 31, w = t >> 5;
    const int b = blockIdx.y;
    const int i0 = (blockIdx.x >> 1) * 128;
    const int cbase = (blockIdx.x & 1) * 128;

    // Build Qext fragments once
    for (int idx = t; idx < 128*32; idx += 256) {
        int q = idx >> 5, c = idx & 31;
        int gi = b*NN + i0 + q;
        float val;
        if (c < 14)       val = g_q2p[(size_t)gi*NQ + c];
        else if (c < 28)  val = (g_sidq[gi] == c - 14) ? 1.f : 0.f;
        else              val = (c == 28) ? 1.f : 0.f;
        int ww = q >> 4, qr = q & 15, ks = c >> 3, ck = c & 7;
        int ln = ((qr & 7) << 2) | (ck & 3);
        int rg = ((ck >> 2) << 1) | (qr >> 3);
        ((unsigned*)&Qf[(ww*4 + ks)*32 + ln])[rg] = tf32r(val);
    }
    __syncthreads();
    uint4 aS[4];
    #pragma unroll
    for (int ks = 0; ks < 4; ks++) aS[ks] = Qf[(w*4 + ks)*32 + lane];

    float acc[16][4];
    #pragma unroll
    for (int nb = 0; nb < 16; nb++) {
        acc[nb][0] = 0.f; acc[nb][1] = 0.f; acc[nb][2] = 0.f; acc[nb][3] = 0.f;
    }
    float m_lo = -INFINITY, m_hi = -INFINITY, l_lo = 0.f, l_hi = 0.f;

    for (int kt = 0; kt < NN/32; kt++) {
        int k0 = kt * 32;
        __syncthreads();
        // Kext fragments
        for (int idx = t; idx < 32*32; idx += 256) {
            int jl = idx >> 5, c = idx & 31;
            int gj = b*NN + k0 + jl;
            float val;
            if (c < 14)       val = g_s2p[(size_t)gj*NQ + c];
            else if (c < 28)  val = g_Ptab[(c - 14)*NQ + g_sids[gj]];
            else              val = (c == 28) ? -10000.f * (float)valid[gj] : 0.f;
            int ks = c >> 3, ck = c & 7;
            int ln = ((jl & 7) << 2) | (ck & 3);
            ((unsigned*)&Kf[((jl >> 3)*4 + ks)*32 + ln])[ck >> 2] = tf32r(val);
        }
        // V tile (tf32-rounded)
        for (int idx = t; idx < 32*32; idx += 256) {
            int kr = idx >> 5, c4 = idx & 31;
            float4 v4 = *(const float4*)(g_vv + ((size_t)(b*NN + k0 + kr))*CC + cbase + c4*4);
            float4 o;
            o.x = __uint_as_float(tf32r(v4.x)); o.y = __uint_as_float(tf32r(v4.y));
            o.z = __uint_as_float(tf32r(v4.z)); o.w = __uint_as_float(tf32r(v4.w));
            *(float4*)&Vs[kr][c4*4] = o;
        }
        __syncthreads();

        // S = Qext . Kext^T   (warp: 16q x 32k)
        float s0[4], s1[4], s2[4], s3[4];
        #pragma unroll
        for (int nb = 0; nb < 4; nb++) {
            float c0 = 0.f, c1 = 0.f, c2 = 0.f, c3 = 0.f;
            #pragma unroll
            for (int ks = 0; ks < 4; ks++) {
                uint2 bv = Kf[(nb*4 + ks)*32 + lane];
                mma8(c0, c1, c2, c3, aS[ks].x, aS[ks].y, aS[ks].z, aS[ks].w, bv.x, bv.y);
            }
            s0[nb] = c0; s1[nb] = c1; s2[nb] = c2; s3[nb] = c3;
        }

        // online softmax (row g = lane>>2 in lo regs, g+8 in hi regs)
        float tlo = -INFINITY, thi = -INFINITY;
        #pragma unroll
        for (int nb = 0; nb < 4; nb++) {
            tlo = fmaxf(tlo, fmaxf(s0[nb], s1[nb]));
            thi = fmaxf(thi, fmaxf(s2[nb], s3[nb]));
        }
        tlo = fmaxf(tlo, __shfl_xor_sync(0xffffffffu, tlo, 1));
        tlo = fmaxf(tlo, __shfl_xor_sync(0xffffffffu, tlo, 2));
        thi = fmaxf(thi, __shfl_xor_sync(0xffffffffu, thi, 1));
        thi = fmaxf(thi, __shfl_xor_sync(0xffffffffu, thi, 2));
        float mn_lo = fmaxf(m_lo, tlo), mn_hi = fmaxf(m_hi, thi);
        float sc_lo = __expf(m_lo - mn_lo), sc_hi = __expf(m_hi - mn_hi);
        m_lo = mn_lo; m_hi = mn_hi;
        float ps_lo = 0.f, ps_hi = 0.f;
        #pragma unroll
        for (int nb = 0; nb < 4; nb++) {
            s0[nb] = __expf(s0[nb] - mn_lo);
            s1[nb] = __expf(s1[nb] - mn_lo);
            s2[nb] = __expf(s2[nb] - mn_hi);
            s3[nb] = __expf(s3[nb] - mn_hi);
            ps_lo += s0[nb] + s1[nb];
            ps_hi += s2[nb] + s3[nb];
        }
        ps_lo += __shfl_xor_sync(0xffffffffu, ps_lo, 1);
        ps_lo += __shfl_xor_sync(0xffffffffu, ps_lo, 2);
        ps_hi += __shfl_xor_sync(0xffffffffu, ps_hi, 1);
        ps_hi += __shfl_xor_sync(0xffffffffu, ps_hi, 2);
        l_lo = l_lo * sc_lo + ps_lo;
        l_hi = l_hi * sc_hi + ps_hi;
        #pragma unroll
        for (int nb = 0; nb < 16; nb++) {
            acc[nb][0] *= sc_lo; acc[nb][1] *= sc_lo;
            acc[nb][2] *= sc_hi; acc[nb][3] *= sc_hi;
        }

        // P (C-frag) -> A-frag via shuffles, then PV MMAs
        const int src0 = (lane & ~3) | ((lane & 3) >> 1);
        const int src2 = src0 + 2;
        const bool odd = lane & 1;
        #pragma unroll
        for (int kb = 0; kb < 4; kb++) {
            unsigned p0 = tf32r(s0[kb]), p1 = tf32r(s1[kb]);
            unsigned p2 = tf32r(s2[kb]), p3 = tf32r(s3[kb]);
            unsigned q00 = __shfl_sync(0xffffffffu, p0, src0);
            unsigned q01 = __shfl_sync(0xffffffffu, p1, src0);
            unsigned q20 = __shfl_sync(0xffffffffu, p0, src2);
            unsigned q21 = __shfl_sync(0xffffffffu, p1, src2);
            unsigned q10 = __shfl_sync(0xffffffffu, p2, src0);
            unsigned q11 = __shfl_sync(0xffffffffu, p3, src0);
            unsigned q30 = __shfl_sync(0xffffffffu, p2, src2);
            unsigned q31 = __shfl_sync(0xffffffffu, p3, src2);
            unsigned a0 = odd ? q01 : q00;
            unsigned a1 = odd ? q11 : q10;
            unsigned a2 = odd ? q21 : q20;
            unsigned a3 = odd ? q31 : q30;
            const float* vr0 = &Vs[kb*8 + (lane & 3)][lane >> 2];
            const float* vr1 = vr0 + 4*136;
            #pragma unroll
            for (int nb = 0; nb < 16; nb++) {
                unsigned b0 = __float_as_uint(vr0[nb*8]);
                unsigned b1 = __float_as_uint(vr1[nb*8]);
                mma8(acc[nb][0], acc[nb][1], acc[nb][2], acc[nb][3], a0, a1, a2, a3, b0, b1);
            }
        }
    }

    // epilogue
    float il_lo = 1.f / l_lo, il_hi = 1.f / l_hi;
    int row_lo = i0 + w*16 + (lane >> 2);
    int col0 = cbase + 2*(lane & 3);
    float* out_lo = g_xattn + ((size_t)b*NN + row_lo)*CC + col0;
    float* out_hi = out_lo + 8*CC;
    #pragma unroll
    for (int nb = 0; nb < 16; nb++) {
        *(float2*)(out_lo + nb*8) = make_float2(acc[nb][0]*il_lo, acc[nb][1]*il_lo);
        *(float2*)(out_hi + nb*8) = make_float2(acc[nb][2]*il_hi, acc[nb][3]*il_hi);
    }
}

// ---------------------------------------------------------------------------
// Launch
// ---------------------------------------------------------------------------
extern "C" void kernel_launch(void* const* d_in, const int* in_sizes, int n_in,
                              void* d_out, int out_size)
{
    (void)in_sizes; (void)n_in; (void)out_size;
    const float* q      = (const float*)d_in[0];
    const float* k      = (const float*)d_in[1];
    const float* v      = (const float*)d_in[2];
    const float* sv     = (const float*)d_in[3];
    const int*   svalid = (const int*)d_in[4];
    const int*   smask  = (const int*)d_in[5];
    const float* Wq     = (const float*)d_in[6];
    const float* Wk     = (const float*)d_in[7];
    const float* Wv     = (const float*)d_in[8];
    const float* Ws     = (const float*)d_in[9];
    const float* Wsq    = (const float*)d_in[10];
    const float* Wsk    = (const float*)d_in[11];
    const float* Wproj  = (const float*)d_in[12];
    const float* Wqs    = (const float*)d_in[13];
    const float* Wks    = (const float*)d_in[14];
    const float* Wvs    = (const float*)d_in[15];
    const float* Wfc    = (const float*)d_in[16];
    const float* bfc    = (const float*)d_in[17];
    const float* lng    = (const float*)d_in[18];
    const float* lnb    = (const float*)d_in[19];
    float* out = (float*)d_out;

    float *p_qs, *p_kk, *p_vv, *p_kh, *p_vh, *p_xa;
    cudaGetSymbolAddress((void**)&p_qs, g_qs);
    cudaGetSymbolAddress((void**)&p_kk, g_kk);
    cudaGetSymbolAddress((void**)&p_vv, g_vv);
    cudaGetSymbolAddress((void**)&p_kh, g_kh);
    cudaGetSymbolAddress((void**)&p_vh, g_vh);
    cudaGetSymbolAddress((void**)&p_xa, g_xattn);

    dim3 g256(2, 128), g512(4, 128);
    prep_kernel<<<1, 256>>>(smask);
    gemm_k256<<<g256, 256>>>(q, Wq, p_qs, 256);
    gemm_k256<<<g256, 256>>>(k, Wk, p_kk, 256);
    gemm_k256<<<g256, 256>>>(v, Wv, p_vv, 256);
    seed_qh_kernel<<<BB*NQ, 256>>>(sv, Ws, Wqs);
    gemm_k256<<<g512, 256>>>(p_kk, Wks, p_kh, 512);
    gemm_k256<<<g512, 256>>>(p_vv, Wvs, p_vh, 512);
    logits_kernel<<<dim3(NN/256, BB), 256>>>(smask);
    softmax_ctx_kernel<<<dim3(NQ, BB), 512>>>();
    proto_kernel<<<BB*NQ, 256>>>(Wfc, bfc, lng, lnb, Wsk, Wsq);
    rowsim_kernel<<<BB*NN/8, 256>>>(smask);
    sinkhorn_kernel<<<8, 512>>>();
    flash_mma<<<dim3(64, BB), 256>>>(svalid);
    gemm_k256<<<g256, 256>>>(p_xa, Wproj, out, 256);
}

// round 14
// speedup vs baseline: 1.7837x; 1.2890x over previous
#include <cuda_runtime.h>
#include <math.h>

#define BB 4
#define NN 4096
#define CC 256
#define NQ 14
#define DK 512
#define NM 15

// ---------------- scratch (device globals; allocation-free) ----------------
__device__ float g_qs[BB*NN*CC];
__device__ float g_kk[BB*NN*CC];
__device__ float g_vv[BB*NN*CC];
__device__ float g_kh[BB*NN*DK];
__device__ float g_vh[BB*NN*DK];
__device__ float g_seed[BB*NQ*CC];
__device__ float g_qh[BB*NQ*DK];
__device__ float g_logits[BB*NQ*NN];
__device__ float g_ctx[BB*NQ*DK];
__device__ float g_cm[BB*NQ*8];
__device__ float g_cS[BB*NQ*8];
__device__ float g_cp[BB*NQ*8*DK];
__device__ float g_pkn[BB*NQ*CC];
__device__ float g_pqn[BB*NQ*CC];
__device__ float g_q2p[BB*NN*NQ];
__device__ int   g_sidq[BB*NN];
__device__ float g_Kmat[BB*NN*NM];
__device__ float g_s2p[BB*NN*NQ];
__device__ int   g_sids[BB*NN];
__device__ float g_rowm[BB*NM];
__device__ float g_Ptab[NQ*NQ];
__device__ float g_xattn[BB*NN*CC];

__device__ __forceinline__ float d4(float4 a, float4 b) {
    return a.x*b.x + a.y*b.y + a.z*b.z + a.w*b.w;
}
__device__ __forceinline__ float wsum(float v) {
    #pragma unroll
    for (int o = 16; o; o >>= 1) v += __shfl_xor_sync(0xffffffffu, v, o);
    return v;
}
__device__ __forceinline__ unsigned tf32r(float x) {
    unsigned y; asm("cvt.rna.tf32.f32 %0, %1;" : "=r"(y) : "f"(x)); return y;
}
__device__ __forceinline__ float tf32f(float x) { return __uint_as_float(tf32r(x)); }
__device__ __forceinline__ void mma8(float& d0, float& d1, float& d2, float& d3,
    unsigned a0, unsigned a1, unsigned a2, unsigned a3, unsigned b0, unsigned b1)
{
    asm volatile("mma.sync.aligned.m16n8k8.row.col.f32.tf32.tf32.f32 "
        "{%0,%1,%2,%3},{%4,%5,%6,%7},{%8,%9},{%0,%1,%2,%3};"
        : "+f"(d0), "+f"(d1), "+f"(d2), "+f"(d3)
        : "r"(a0), "r"(a1), "r"(a2), "r"(a3), "r"(b0), "r"(b1));
}
__device__ __forceinline__ float dsmem_ld_f32(unsigned addr, unsigned peer) {
    unsigned r; float v;
    asm volatile("mapa.shared::cluster.u32 %0, %1, %2;" : "=r"(r) : "r"(addr), "r"(peer));
    asm volatile("ld.shared::cluster.f32 %0, [%1];" : "=f"(v) : "r"(r));
    return v;
}

// ---------------------------------------------------------------------------
// fp32 GEMM, K=256: Y[16384, NC] = X[16384,256] @ W[256,NC]. 128x128, 8x8 micro.
// Used where tf32 would risk argmax flips (q/k/v projections, final Wproj).
// ---------------------------------------------------------------------------
__device__ __forceinline__ void gemm_body(const float* __restrict__ X,
                                          const float* __restrict__ W,
                                          float* __restrict__ Y, int NC)
{
    __shared__ __align__(16) float Xs[16][128];
    __shared__ __align__(16) float Bs[16][128];
    const int t  = threadIdx.x;
    const int m0 = blockIdx.y * 128;
    const int n0 = blockIdx.x * 128;
    const int tx = t & 15, ty = t >> 4;

    float acc[8][8];
    #pragma unroll
    for (int i = 0; i < 8; i++)
        #pragma unroll
        for (int j = 0; j < 8; j++) acc[i][j] = 0.f;

    for (int kt = 0; kt < 256; kt += 16) {
        __syncthreads();
        #pragma unroll
        for (int h = 0; h < 2; h++) {
            int f4  = t + 256 * h;
            int row = f4 >> 2, kq = f4 & 3;
            float4 xv = *(const float4*)(X + (size_t)(m0 + row) * 256 + kt + kq * 4);
            Xs[kq*4+0][row] = xv.x; Xs[kq*4+1][row] = xv.y;
            Xs[kq*4+2][row] = xv.z; Xs[kq*4+3][row] = xv.w;
            int r = f4 >> 5, c4 = f4 & 31;
            *(float4*)&Bs[r][c4*4] = *(const float4*)(W + (size_t)(kt + r) * NC + n0 + c4 * 4);
        }
        __syncthreads();
        #pragma unroll
        for (int kk2 = 0; kk2 < 16; kk2++) {
            float4 a0 = *(float4*)&Xs[kk2][ty*8];
            float4 a1 = *(float4*)&Xs[kk2][ty*8+4];
            float4 b0 = *(float4*)&Bs[kk2][tx*8];
            float4 b1 = *(float4*)&Bs[kk2][tx*8+4];
            float av[8] = {a0.x,a0.y,a0.z,a0.w,a1.x,a1.y,a1.z,a1.w};
            float bv[8] = {b0.x,b0.y,b0.z,b0.w,b1.x,b1.y,b1.z,b1.w};
            #pragma unroll
            for (int i = 0; i < 8; i++)
                #pragma unroll
                for (int j = 0; j < 8; j++) acc[i][j] += av[i] * bv[j];
        }
    }
    #pragma unroll
    for (int i = 0; i < 8; i++) {
        float* yr = Y + (size_t)(m0 + ty*8 + i) * NC + n0 + tx*8;
        *(float4*)yr       = make_float4(acc[i][0], acc[i][1], acc[i][2], acc[i][3]);
        *(float4*)(yr + 4) = make_float4(acc[i][4], acc[i][5], acc[i][6], acc[i][7]);
    }
}

__global__ __launch_bounds__(256) void gemm_k256(const float* __restrict__ X,
                                                 const float* __restrict__ W,
                                                 float* __restrict__ Y, int NC)
{
    gemm_body(X, W, Y, NC);
}

// q/k/v projections in one launch (grid.z selects)
__global__ __launch_bounds__(256) void gemm_k256_x3(
    const float* __restrict__ x0, const float* __restrict__ x1, const float* __restrict__ x2,
    const float* __restrict__ w0, const float* __restrict__ w1, const float* __restrict__ w2,
    float* __restrict__ y0, float* __restrict__ y1, float* __restrict__ y2)
{
    const float* X = blockIdx.z == 0 ? x0 : (blockIdx.z == 1 ? x1 : x2);
    const float* W = blockIdx.z == 0 ? w0 : (blockIdx.z == 1 ? w1 : w2);
    float*       Y = blockIdx.z == 0 ? y0 : (blockIdx.z == 1 ? y1 : y2);
    gemm_body(X, W, Y, 256);
}

// ---------------------------------------------------------------------------
// tf32 MMA GEMM for kh/vh (argmax influence damped through softmax -> safe).
// Y[16384, 512] = X[16384,256] @ W[256,512]; grid (4, 128, 2).
// ---------------------------------------------------------------------------
__global__ __launch_bounds__(256) void gemm_tf32_x2(
    const float* __restrict__ x0, const float* __restrict__ w0, float* __restrict__ y0,
    const float* __restrict__ x1, const float* __restrict__ w1, float* __restrict__ y1,
    int NC)
{
    __shared__ __align__(16) float Xs[128][36];   // row-major, pad 36 (conflict-free frags)
    __shared__ __align__(16) float Ws[32][136];   // k-major,  pad 136

    const int t = threadIdx.x, lane = t & 31, w = t >> 5;
    const int m0 = blockIdx.y * 128, n0 = blockIdx.x * 128;
    const float* X = blockIdx.z ? x1 : x0;
    const float* W = blockIdx.z ? w1 : w0;
    float*       Y = blockIdx.z ? y1 : y0;
    const int wm = w >> 2, wn = w & 3;            // 2 x 4 warps -> 64 x 32 per warp

    float acc[4][4][4];
    #pragma unroll
    for (int mi = 0; mi < 4; mi++)
        #pragma unroll
        for (int ni = 0; ni < 4; ni++) {
            acc[mi][ni][0] = 0.f; acc[mi][ni][1] = 0.f;
            acc[mi][ni][2] = 0.f; acc[mi][ni][3] = 0.f;
        }

    for (int kt = 0; kt < 256; kt += 32) {
        __syncthreads();
        #pragma unroll
        for (int i = 0; i < 4; i++) {
            int f4 = t + 256*i;
            int row = f4 >> 3, kq = f4 & 7;
            float4 xv = *(const float4*)(X + (size_t)(m0 + row)*256 + kt + kq*4);
            float* d = &Xs[row][kq*4];
            d[0] = tf32f(xv.x); d[1] = tf32f(xv.y); d[2] = tf32f(xv.z); d[3] = tf32f(xv.w);
        }
        #pragma unroll
        for (int i = 0; i < 4; i++) {
            int f4 = t + 256*i;
            int r = f4 >> 5, c4 = f4 & 31;
            float4 wv = *(const float4*)(W + (size_t)(kt + r)*NC + n0 + c4*4);
            float4 o;
            o.x = tf32f(wv.x); o.y = tf32f(wv.y); o.z = tf32f(wv.z); o.w = tf32f(wv.w);
            *(float4*)&Ws[r][c4*4] = o;
        }
        __syncthreads();
        #pragma unroll
        for (int ks = 0; ks < 4; ks++) {
            const int kk0 = ks*8;
            unsigned a[4][4], bf[4][2];
            #pragma unroll
            for (int mi = 0; mi < 4; mi++) {
                const float* xp = &Xs[wm*64 + mi*16 + (lane >> 2)][kk0 + (lane & 3)];
                a[mi][0] = __float_as_uint(xp[0]);
                a[mi][1] = __float_as_uint(xp[8*36]);
                a[mi][2] = __float_as_uint(xp[4]);
                a[mi][3] = __float_as_uint(xp[8*36 + 4]);
            }
            #pragma unroll
            for (int ni = 0; ni < 4; ni++) {
                const float* wp = &Ws[kk0 + (lane & 3)][wn*32 + ni*8 + (lane >> 2)];
                bf[ni][0] = __float_as_uint(wp[0]);
                bf[ni][1] = __float_as_uint(wp[4*136]);
            }
            #pragma unroll
            for (int mi = 0; mi < 4; mi++)
                #pragma unroll
                for (int ni = 0; ni < 4; ni++)
                    mma8(acc[mi][ni][0], acc[mi][ni][1], acc[mi][ni][2], acc[mi][ni][3],
                         a[mi][0], a[mi][1], a[mi][2], a[mi][3], bf[ni][0], bf[ni][1]);
        }
    }
    #pragma unroll
    for (int mi = 0; mi < 4; mi++) {
        int row = m0 + wm*64 + mi*16 + (lane >> 2);
        #pragma unroll
        for (int ni = 0; ni < 4; ni++) {
            int col = n0 + wn*32 + ni*8 + 2*(lane & 3);
            *(float2*)(Y + (size_t)row*NC + col)     = make_float2(acc[mi][ni][0], acc[mi][ni][1]);
            *(float2*)(Y + (size_t)(row+8)*NC + col) = make_float2(acc[mi][ni][2], acc[mi][ni][3]);
        }
    }
}

// ---------------------------------------------------------------------------
// Prep: alignment table, row marginals
// ---------------------------------------------------------------------------
__global__ __launch_bounds__(256) void prep_kernel(const int* __restrict__ supp_mask)
{
    int t = threadIdx.x;
    if (t < NQ*NQ) {
        int s = t / NQ, q = t % NQ;
        int prod = (2*s + 3) * (2*q + 3);
        int r = (int)(sqrtf((float)prod) + 0.5f);
        g_Ptab[t] = (r*r == prod) ? 0.f : -10000.f;
    }
    __shared__ int red[256];
    int b = t >> 6, j = t & 63;
    int cnt = 0;
    for (int i = j; i < NN; i += 64) cnt += (supp_mask[b*NN + i] == 0);
    red[t] = cnt;
    __syncthreads();
    for (int o = 32; o; o >>= 1) { if (j < o) red[t] += red[t + o]; __syncthreads(); }
    if (j == 0) {
        float nbg = (float)red[t];
        float nfg = (float)NN - nbg;
        for (int m2 = 0; m2 < NQ; m2++) g_rowm[b*NM + m2] = nfg / (float)(NQ * NN);
        g_rowm[b*NM + NQ] = nbg / (float)NN;
    }
}

// ---------------------------------------------------------------------------
// seed[b,q,d] = sum_c sv[b,c,q]*Ws[c,d];  qh = seed @ Wqs
// ---------------------------------------------------------------------------
__global__ __launch_bounds__(256) void seed_qh_kernel(const float* __restrict__ sv,
                                                      const float* __restrict__ Ws,
                                                      const float* __restrict__ Wqs)
{
    __shared__ float svc[CC];
    __shared__ float sd[CC];
    int bq = blockIdx.x;
    int b = bq / NQ, q = bq % NQ;
    int t = threadIdx.x;
    svc[t] = sv[((size_t)b*CC + t)*NQ + q];
    __syncthreads();
    float a = 0.f;
    #pragma unroll 8
    for (int c = 0; c < CC; c++) a += svc[c] * Ws[(size_t)c*CC + t];
    g_seed[(size_t)bq*CC + t] = a;
    sd[t] = a;
    __syncthreads();
    #pragma unroll
    for (int h = 0; h < 2; h++) {
        int d = t + 256*h;
        float a2 = 0.f;
        #pragma unroll 8
        for (int c = 0; c < CC; c++) a2 += sd[c] * Wqs[(size_t)c*DK + d];
        g_qh[(size_t)bq*DK + d] = a2;
    }
}

// ---------------------------------------------------------------------------
// logits[b,q,n] = qh.kh/sqrt(512), masked -1e9 where supp_mask==0
// ---------------------------------------------------------------------------
__global__ __launch_bounds__(256) void logits_kernel(const int* __restrict__ supp_mask)
{
    __shared__ __align__(16) float qh_s[NQ*DK];
    int b = blockIdx.y;
    int n = blockIdx.x * 256 + threadIdx.x;
    for (int i = threadIdx.x; i < NQ*DK; i += 256) qh_s[i] = g_qh[(size_t)b*NQ*DK + i];
    __syncthreads();
    const float4* kh4 = (const float4*)(g_kh + ((size_t)b*NN + n) * DK);
    float acc[NQ];
    #pragma unroll
    for (int q = 0; q < NQ; q++) acc[q] = 0.f;
    for (int c4 = 0; c4 < DK/4; c4++) {
        float4 kv = kh4[c4];
        #pragma unroll
        for (int q = 0; q < NQ; q++) {
            float4 qv = *(float4*)&qh_s[q*DK + c4*4];
            acc[q] += d4(kv, qv);
        }
    }
    const float sc = 0.044194173824159216f;  // 1/sqrt(512)
    bool masked = (supp_mask[b*NN + n] == 0);
    #pragma unroll
    for (int q = 0; q < NQ; q++)
        g_logits[((size_t)b*NQ + q)*NN + n] = masked ? -1e9f : acc[q] * sc;
}

// ---------------------------------------------------------------------------
// ctx partials: per (q,b,chunk of 512 keys): local max/sum + partial ctx.
// ---------------------------------------------------------------------------
__global__ __launch_bounds__(512) void ctx_part_kernel()
{
    __shared__ float ls[512];
    __shared__ float red[512];
    int q = blockIdx.x, b = blockIdx.y, c = blockIdx.z, t = threadIdx.x;
    const float* lrow = g_logits + ((size_t)b*NQ + q)*NN + c*512;
    float v = lrow[t];
    red[t] = v;
    __syncthreads();
    for (int o = 256; o; o >>= 1) { if (t < o) red[t] = fmaxf(red[t], red[t+o]); __syncthreads(); }
    float m = red[0];
    __syncthreads();
    float p = expf(v - m);
    ls[t] = p;
    red[t] = p;
    __syncthreads();
    for (int o = 256; o; o >>= 1) { if (t < o) red[t] += red[t+o]; __syncthreads(); }
    float S = red[0];
    __syncthreads();
    const float* vb = g_vh + ((size_t)b*NN + c*512)*DK;
    float a0 = 0.f, a1 = 0.f, a2 = 0.f, a3 = 0.f;
    for (int n = 0; n < 512; n += 4) {
        a0 += ls[n+0] * vb[(size_t)(n+0)*DK + t];
        a1 += ls[n+1] * vb[(size_t)(n+1)*DK + t];
        a2 += ls[n+2] * vb[(size_t)(n+2)*DK + t];
        a3 += ls[n+3] * vb[(size_t)(n+3)*DK + t];
    }
    int idx = (b*NQ + q)*8 + c;
    if (t == 0) { g_cm[idx] = m; g_cS[idx] = S; }
    g_cp[(size_t)idx*DK + t] = (a0 + a1) + (a2 + a3);
}

__global__ __launch_bounds__(512) void ctx_comb_kernel()
{
    int q = blockIdx.x, b = blockIdx.y, t = threadIdx.x;
    int base = (b*NQ + q)*8;
    float m = -INFINITY;
    #pragma unroll
    for (int c = 0; c < 8; c++) m = fmaxf(m, g_cm[base + c]);
    float S = 0.f, ctx = 0.f;
    #pragma unroll
    for (int c = 0; c < 8; c++) {
        float e = expf(g_cm[base + c] - m);
        S   += g_cS[base + c] * e;
        ctx += g_cp[(size_t)(base + c)*DK + t] * e;
    }
    g_ctx[((size_t)b*NQ + q)*DK + t] = ctx / S;
}

// ---------------------------------------------------------------------------
// prototypes = LN(ctx@Wfc + bfc + seed); pk/pq l2-normalized
// ---------------------------------------------------------------------------
__global__ __launch_bounds__(256) void proto_kernel(const float* __restrict__ Wfc,
    const float* __restrict__ bfc, const float* __restrict__ ln_g,
    const float* __restrict__ ln_b, const float* __restrict__ Wsk,
    const float* __restrict__ Wsq)
{
    __shared__ float cs[DK];
    __shared__ float ps[CC];
    __shared__ float red[256];
    int bq = blockIdx.x, t = threadIdx.x;
    cs[t]       = g_ctx[(size_t)bq*DK + t];
    cs[t + 256] = g_ctx[(size_t)bq*DK + t + 256];
    __syncthreads();
    float pre = bfc[t] + g_seed[(size_t)bq*CC + t];
    #pragma unroll 8
    for (int k2 = 0; k2 < DK; k2++) pre += cs[k2] * Wfc[(size_t)k2*CC + t];
    red[t] = pre;
    __syncthreads();
    for (int o = 128; o; o >>= 1) { if (t < o) red[t] += red[t+o]; __syncthreads(); }
    float mu = red[0] * (1.f/256.f);
    __syncthreads();
    float dd = pre - mu;
    red[t] = dd * dd;
    __syncthreads();
    for (int o = 128; o; o >>= 1) { if (t < o) red[t] += red[t+o]; __syncthreads(); }
    float var = red[0] * (1.f/256.f);
    __syncthreads();
    float prot = dd / sqrtf(var + 1e-5f) * ln_g[t] + ln_b[t];
    ps[t] = prot;
    __syncthreads();
    float pk = 0.f, pq = 0.f;
    #pragma unroll 8
    for (int c = 0; c < CC; c++) {
        float pv = ps[c];
        pk += pv * Wsk[(size_t)c*CC + t];
        pq += pv * Wsq[(size_t)c*CC + t];
    }
    red[t] = pk * pk;
    __syncthreads();
    for (int o = 128; o; o >>= 1) { if (t < o) red[t] += red[t+o]; __syncthreads(); }
    float nk = sqrtf(red[0]);
    __syncthreads();
    red[t] = pq * pq;
    __syncthreads();
    for (int o = 128; o; o >>= 1) { if (t < o) red[t] += red[t+o]; __syncthreads(); }
    float nq2 = sqrtf(red[0]);
    g_pkn[(size_t)bq*CC + t] = pk / fmaxf(nk,  1e-12f);
    g_pqn[(size_t)bq*CC + t] = pq / fmaxf(nq2, 1e-12f);
}

// ---------------------------------------------------------------------------
// Per-row: q2p (+argmax), Kmat = exp(-cost/0.05). One warp per row.
// ---------------------------------------------------------------------------
__global__ __launch_bounds__(256) void rowsim_kernel(const int* __restrict__ supp_mask)
{
    __shared__ __align__(16) float pkn_s[NQ*CC];
    __shared__ __align__(16) float pqn_s[NQ*CC];
    int t = threadIdx.x, lane = t & 31, wid = t >> 5;
    int g = blockIdx.x * 8 + wid;
    int b = g >> 12;
    for (int i = t; i < NQ*CC; i += 256) {
        pkn_s[i] = g_pkn[(size_t)b*NQ*CC + i];
        pqn_s[i] = g_pqn[(size_t)b*NQ*CC + i];
    }
    __syncthreads();
    const float* qrow = g_qs + (size_t)g*CC;
    const float* krow = g_kk + (size_t)g*CC;
    float4 q0 = *(const float4*)(qrow + lane*4);
    float4 q1 = *(const float4*)(qrow + 128 + lane*4);
    float4 k0 = *(const float4*)(krow + lane*4);
    float4 k1 = *(const float4*)(krow + 128 + lane*4);
    float rnq = 1.f / fmaxf(sqrtf(wsum(d4(q0,q0) + d4(q1,q1))), 1e-12f);
    float rnk = 1.f / fmaxf(sqrtf(wsum(d4(k0,k0) + d4(k1,k1))), 1e-12f);
    float myq2p = 0.f, myK = 0.f;
    float best = -INFINITY; int bk = 0;
    #pragma unroll
    for (int k2 = 0; k2 < NQ; k2++) {
        float4 p0 = *(float4*)&pkn_s[k2*CC + lane*4];
        float4 p1 = *(float4*)&pkn_s[k2*CC + 128 + lane*4];
        float val = wsum(d4(q0,p0) + d4(q1,p1)) * rnq;
        if (val > best) { best = val; bk = k2; }
        if (lane == k2) myq2p = val;
        float4 r0 = *(float4*)&pqn_s[k2*CC + lane*4];
        float4 r1 = *(float4*)&pqn_s[k2*CC + 128 + lane*4];
        float a = wsum(d4(k0,r0) + d4(k1,r1)) * rnk;
        if (lane == k2) myK = expf(20.f * (a - 1.f));
    }
    if (lane < NQ) {
        g_q2p[(size_t)g*NQ + lane]  = myq2p;
        g_Kmat[(size_t)g*NM + lane] = myK;
    }
    if (lane == NQ)
        g_Kmat[(size_t)g*NM + NQ] = (supp_mask[g] > 0) ? expf(-40.f) : 1.f;
    if (lane == 0) g_sidq[g] = bk;
}

// ---------------------------------------------------------------------------
// Sinkhorn: clusters of 2 CTAs (one cluster per batch). K in registers; the
// 15 column-partials are exchanged via DSMEM with barrier.cluster (double-
// buffered). Arithmetic order identical to the passing global-barrier version.
// ---------------------------------------------------------------------------
__global__ __launch_bounds__(512) __cluster_dims__(2,1,1) void sinkhorn_kernel()
{
    __shared__ float sred[16*NM];
    __shared__ float v_s[NM];
    __shared__ float part_s[2][NM];
    int t = threadIdx.x, lane = t & 31, wid = t >> 5;
    int b = blockIdx.x >> 1;
    unsigned rank = blockIdx.x & 1;          // cluster ctarank (cluster = 2 consecutive blocks)
    unsigned part_base = (unsigned)__cvta_generic_to_shared(&part_s[0][0]);

    float Kl[4][NM];
    int rowg[4];
    #pragma unroll
    for (int i = 0; i < 4; i++) {
        int n = (int)rank*2048 + i*512 + t;
        rowg[i] = b*NN + n;
        #pragma unroll
        for (int j = 0; j < NM; j++) Kl[i][j] = g_Kmat[(size_t)rowg[i]*NM + j];
    }
    float u[4] = {1.f/NN, 1.f/NN, 1.f/NN, 1.f/NN};

    for (int iter = 0; iter < 100; iter++) {
        #pragma unroll
        for (int j = 0; j < NM; j++) {
            float x = Kl[0][j]*u[0] + Kl[1][j]*u[1] + Kl[2][j]*u[2] + Kl[3][j]*u[3];
            x = wsum(x);
            if (lane == 0) sred[wid*NM + j] = x;
        }
        __syncthreads();
        if (t < NM) {
            float bp = 0.f;
            #pragma unroll
            for (int w2 = 0; w2 < 16; w2++) bp += sred[w2*NM + t];
            part_s[iter & 1][t] = bp;
        }
        asm volatile("barrier.cluster.arrive.aligned;" ::: "memory");
        asm volatile("barrier.cluster.wait.aligned;" ::: "memory");
        if (t < NM) {
            float own  = part_s[iter & 1][t];
            float peer = dsmem_ld_f32(part_base + ((iter & 1)*NM + t)*4u, rank ^ 1u);
            float h0 = rank == 0 ? own : peer;
            float h1 = rank == 0 ? peer : own;
            v_s[t] = g_rowm[b*NM + t] / ((h0 + h1) + 1e-16f);
        }
        __syncthreads();
        #pragma unroll
        for (int i = 0; i < 4; i++) {
            float dsum = 0.f;
            #pragma unroll
            for (int j = 0; j < NM; j++) dsum += Kl[i][j]*v_s[j];
            u[i] = (1.f/NN) / (dsum + 1e-16f);
        }
    }
    // peer may still be dsmem-reading our part_s; sync before epilogue/exit
    asm volatile("barrier.cluster.arrive.aligned;" ::: "memory");
    asm volatile("barrier.cluster.wait.aligned;" ::: "memory");

    #pragma unroll
    for (int i = 0; i < 4; i++) {
        float best = -INFINITY; int bk = 0;
        #pragma unroll
        for (int j = 0; j < NQ; j++) {
            float tv = fmaxf(u[i]*Kl[i][j]*v_s[j]*(float)NN, 0.f);
            g_s2p[(size_t)rowg[i]*NQ + j] = tv;
            if (tv > best) { best = tv; bk = j; }
        }
        g_sids[rowg[i]] = bk;
    }
}

// ---------------------------------------------------------------------------
// Flash attention via tf32 mma.m16n8k8 (unchanged from round 13).
// ---------------------------------------------------------------------------
__global__ __launch_bounds__(256, 2) void flash_mma(const int* __restrict__ valid)
{
    __shared__ uint4 Qf[8*4*32];
    __shared__ uint2 Kf[4*4*32];
    __shared__ float Vs[32][136];

    const int t = threadIdx.x, lane = t & 31, w = t >> 5;
    const int b = blockIdx.y;
    const int i0 = (blockIdx.x >> 1) * 128;
    const int cbase = (blockIdx.x & 1) * 128;

    for (int idx = t; idx < 128*32; idx += 256) {
        int q = idx >> 5, c = idx & 31;
        int gi = b*NN + i0 + q;
        float val;
        if (c < 14)       val = g_q2p[(size_t)gi*NQ + c];
        else if (c < 28)  val = (g_sidq[gi] == c - 14) ? 1.f : 0.f;
        else              val = (c == 28) ? 1.f : 0.f;
        int ww = q >> 4, qr = q & 15, ks = c >> 3, ck = c & 7;
        int ln = ((qr & 7) << 2) | (ck & 3);
        int rg = ((ck >> 2) << 1) | (qr >> 3);
        ((unsigned*)&Qf[(ww*4 + ks)*32 + ln])[rg] = tf32r(val);
    }
    __syncthreads();
    uint4 aS[4];
    #pragma unroll
    for (int ks = 0; ks < 4; ks++) aS[ks] = Qf[(w*4 + ks)*32 + lane];

    float acc[16][4];
    #pragma unroll
    for (int nb = 0; nb < 16; nb++) {
        acc[nb][0] = 0.f; acc[nb][1] = 0.f; acc[nb][2] = 0.f; acc[nb][3] = 0.f;
    }
    float m_lo = -INFINITY, m_hi = -INFINITY, l_lo = 0.f, l_hi = 0.f;

    for (int kt = 0; kt < NN/32; kt++) {
        int k0 = kt * 32;
        __syncthreads();
        for (int idx = t; idx < 32*32; idx += 256) {
            int jl = idx >> 5, c = idx & 31;
            int gj = b*NN + k0 + jl;
            float val;
            if (c < 14)       val = g_s2p[(size_t)gj*NQ + c];
            else if (c < 28)  val = g_Ptab[(c - 14)*NQ + g_sids[gj]];
            else              val = (c == 28) ? -10000.f * (float)valid[gj] : 0.f;
            int ks = c >> 3, ck = c & 7;
            int ln = ((jl & 7) << 2) | (ck & 3);
            ((unsigned*)&Kf[((jl >> 3)*4 + ks)*32 + ln])[ck >> 2] = tf32r(val);
        }
        for (int idx = t; idx < 32*32; idx += 256) {
            int kr = idx >> 5, c4 = idx & 31;
            float4 v4 = *(const float4*)(g_vv + ((size_t)(b*NN + k0 + kr))*CC + cbase + c4*4);
            float4 o;
            o.x = tf32f(v4.x); o.y = tf32f(v4.y); o.z = tf32f(v4.z); o.w = tf32f(v4.w);
            *(float4*)&Vs[kr][c4*4] = o;
        }
        __syncthreads();

        float s0[4], s1[4], s2[4], s3[4];
        #pragma unroll
        for (int nb = 0; nb < 4; nb++) {
            float c0 = 0.f, c1 = 0.f, c2 = 0.f, c3 = 0.f;
            #pragma unroll
            for (int ks = 0; ks < 4; ks++) {
                uint2 bv = Kf[(nb*4 + ks)*32 + lane];
                mma8(c0, c1, c2, c3, aS[ks].x, aS[ks].y, aS[ks].z, aS[ks].w, bv.x, bv.y);
            }
            s0[nb] = c0; s1[nb] = c1; s2[nb] = c2; s3[nb] = c3;
        }

        float tlo = -INFINITY, thi = -INFINITY;
        #pragma unroll
        for (int nb = 0; nb < 4; nb++) {
            tlo = fmaxf(tlo, fmaxf(s0[nb], s1[nb]));
            thi = fmaxf(thi, fmaxf(s2[nb], s3[nb]));
        }
        tlo = fmaxf(tlo, __shfl_xor_sync(0xffffffffu, tlo, 1));
        tlo = fmaxf(tlo, __shfl_xor_sync(0xffffffffu, tlo, 2));
        thi = fmaxf(thi, __shfl_xor_sync(0xffffffffu, thi, 1));
        thi = fmaxf(thi, __shfl_xor_sync(0xffffffffu, thi, 2));
        float mn_lo = fmaxf(m_lo, tlo), mn_hi = fmaxf(m_hi, thi);
        float sc_lo = __expf(m_lo - mn_lo), sc_hi = __expf(m_hi - mn_hi);
        m_lo = mn_lo; m_hi = mn_hi;
        float ps_lo = 0.f, ps_hi = 0.f;
        #pragma unroll
        for (int nb = 0; nb < 4; nb++) {
            s0[nb] = __expf(s0[nb] - mn_lo);
            s1[nb] = __expf(s1[nb] - mn_lo);
            s2[nb] = __expf(s2[nb] - mn_hi);
            s3[nb] = __expf(s3[nb] - mn_hi);
            ps_lo += s0[nb] + s1[nb];
            ps_hi += s2[nb] + s3[nb];
        }
        ps_lo += __shfl_xor_sync(0xffffffffu, ps_lo, 1);
        ps_lo += __shfl_xor_sync(0xffffffffu, ps_lo, 2);
        ps_hi += __shfl_xor_sync(0xffffffffu, ps_hi, 1);
        ps_hi += __shfl_xor_sync(0xffffffffu, ps_hi, 2);
        l_lo = l_lo * sc_lo + ps_lo;
        l_hi = l_hi * sc_hi + ps_hi;
        #pragma unroll
        for (int nb = 0; nb < 16; nb++) {
            acc[nb][0] *= sc_lo; acc[nb][1] *= sc_lo;
            acc[nb][2] *= sc_hi; acc[nb][3] *= sc_hi;
        }

        const int src0 = (lane & ~3) | ((lane & 3) >> 1);
        const int src2 = src0 + 2;
        const bool odd = lane & 1;
        #pragma unroll
        for (int kb = 0; kb < 4; kb++) {
            unsigned p0 = tf32r(s0[kb]), p1 = tf32r(s1[kb]);
            unsigned p2 = tf32r(s2[kb]), p3 = tf32r(s3[kb]);
            unsigned q00 = __shfl_sync(0xffffffffu, p0, src0);
            unsigned q01 = __shfl_sync(0xffffffffu, p1, src0);
            unsigned q20 = __shfl_sync(0xffffffffu, p0, src2);
            unsigned q21 = __shfl_sync(0xffffffffu, p1, src2);
            unsigned q10 = __shfl_sync(0xffffffffu, p2, src0);
            unsigned q11 = __shfl_sync(0xffffffffu, p3, src0);
            unsigned q30 = __shfl_sync(0xffffffffu, p2, src2);
            unsigned q31 = __shfl_sync(0xffffffffu, p3, src2);
            unsigned a0 = odd ? q01 : q00;
            unsigned a1 = odd ? q11 : q10;
            unsigned a2 = odd ? q21 : q20;
            unsigned a3 = odd ? q31 : q30;
            const float* vr0 = &Vs[kb*8 + (lane & 3)][lane >> 2];
            const float* vr1 = vr0 + 4*136;
            #pragma unroll
            for (int nb = 0; nb < 16; nb++) {
                unsigned b0 = __float_as_uint(vr0[nb*8]);
                unsigned b1 = __float_as_uint(vr1[nb*8]);
                mma8(acc[nb][0], acc[nb][1], acc[nb][2], acc[nb][3], a0, a1, a2, a3, b0, b1);
            }
        }
    }

    float il_lo = 1.f / l_lo, il_hi = 1.f / l_hi;
    int row_lo = i0 + w*16 + (lane >> 2);
    int col0 = cbase + 2*(lane & 3);
    float* out_lo = g_xattn + ((size_t)b*NN + row_lo)*CC + col0;
    float* out_hi = out_lo + 8*CC;
    #pragma unroll
    for (int nb = 0; nb < 16; nb++) {
        *(float2*)(out_lo + nb*8) = make_float2(acc[nb][0]*il_lo, acc[nb][1]*il_lo);
        *(float2*)(out_hi + nb*8) = make_float2(acc[nb][2]*il_hi, acc[nb][3]*il_hi);
    }
}

// ---------------------------------------------------------------------------
// Launch
// ---------------------------------------------------------------------------
extern "C" void kernel_launch(void* const* d_in, const int* in_sizes, int n_in,
                              void* d_out, int out_size)
{
    (void)in_sizes; (void)n_in; (void)out_size;
    const float* q      = (const float*)d_in[0];
    const float* k      = (const float*)d_in[1];
    const float* v      = (const float*)d_in[2];
    const float* sv     = (const float*)d_in[3];
    const int*   svalid = (const int*)d_in[4];
    const int*   smask  = (const int*)d_in[5];
    const float* Wq     = (const float*)d_in[6];
    const float* Wk     = (const float*)d_in[7];
    const float* Wv     = (const float*)d_in[8];
    const float* Ws     = (const float*)d_in[9];
    const float* Wsq    = (const float*)d_in[10];
    const float* Wsk    = (const float*)d_in[11];
    const float* Wproj  = (const float*)d_in[12];
    const float* Wqs    = (const float*)d_in[13];
    const float* Wks    = (const float*)d_in[14];
    const float* Wvs    = (const float*)d_in[15];
    const float* Wfc    = (const float*)d_in[16];
    const float* bfc    = (const float*)d_in[17];
    const float* lng    = (const float*)d_in[18];
    const float* lnb    = (const float*)d_in[19];
    float* out = (float*)d_out;

    float *p_qs, *p_kk, *p_vv, *p_kh, *p_vh, *p_xa;
    cudaGetSymbolAddress((void**)&p_qs, g_qs);
    cudaGetSymbolAddress((void**)&p_kk, g_kk);
    cudaGetSymbolAddress((void**)&p_vv, g_vv);
    cudaGetSymbolAddress((void**)&p_kh, g_kh);
    cudaGetSymbolAddress((void**)&p_vh, g_vh);
    cudaGetSymbolAddress((void**)&p_xa, g_xattn);

    prep_kernel<<<1, 256>>>(smask);
    gemm_k256_x3<<<dim3(2, 128, 3), 256>>>(q, k, v, Wq, Wk, Wv, p_qs, p_kk, p_vv);
    seed_qh_kernel<<<BB*NQ, 256>>>(sv, Ws, Wqs);
    gemm_tf32_x2<<<dim3(4, 128, 2), 256>>>(p_kk, Wks, p_kh, p_vv, Wvs, p_vh, 512);
    logits_kernel<<<dim3(NN/256, BB), 256>>>(smask);
    ctx_part_kernel<<<dim3(NQ, BB, 8), 512>>>();
    ctx_comb_kernel<<<dim3(NQ, BB), 512>>>();
    proto_kernel<<<BB*NQ, 256>>>(Wfc, bfc, lng, lnb, Wsk, Wsq);
    rowsim_kernel<<<BB*NN/8, 256>>>(smask);
    sinkhorn_kernel<<<8, 512>>>();
    flash_mma<<<dim3(64, BB), 256>>>(svalid);
    gemm_k256<<<dim3(2, 128), 256>>>(p_xa, Wproj, out, 256);
}

// round 15
// speedup vs baseline: 2.0661x; 1.1583x over previous
#include <cuda_runtime.h>
#include <math.h>

#define BB 4
#define NN 4096
#define CC 256
#define NQ 14
#define DK 512
#define NM 15

// ---------------- scratch (device globals; allocation-free) ----------------
__device__ float g_qs[BB*NN*CC];
__device__ float g_kk[BB*NN*CC];
__device__ float g_vv[BB*NN*CC];
__device__ float g_kh[BB*NN*DK];
__device__ float g_vh[BB*NN*DK];
__device__ float g_seed[BB*NQ*CC];
__device__ float g_qh[BB*NQ*DK];
__device__ float g_logits[BB*NQ*NN];
__device__ float g_ctx[BB*NQ*DK];
__device__ float g_cm[BB*NQ*8];
__device__ float g_cS[BB*NQ*8];
__device__ float g_cp[BB*NQ*8*DK];
__device__ float g_pkn[BB*NQ*CC];
__device__ float g_pqn[BB*NQ*CC];
__device__ float g_q2p[BB*NN*NQ];
__device__ int   g_sidq[BB*NN];
__device__ float g_Kmat[BB*NN*NM];
__device__ float g_s2p[BB*NN*NQ];
__device__ int   g_sids[BB*NN];
__device__ float g_rowm[BB*NM];
__device__ float g_Ptab[NQ*NQ];
__device__ unsigned g_alignbits[NQ];
__device__ float g_rowmaxtab[BB*NQ];
__device__ float g_xattn[BB*NN*CC];

__device__ __forceinline__ float d4(float4 a, float4 b) {
    return a.x*b.x + a.y*b.y + a.z*b.z + a.w*b.w;
}
__device__ __forceinline__ float wsum(float v) {
    #pragma unroll
    for (int o = 16; o; o >>= 1) v += __shfl_xor_sync(0xffffffffu, v, o);
    return v;
}
__device__ __forceinline__ unsigned tf32r(float x) {
    unsigned y; asm("cvt.rna.tf32.f32 %0, %1;" : "=r"(y) : "f"(x)); return y;
}
__device__ __forceinline__ float tf32f(float x) { return __uint_as_float(tf32r(x)); }
__device__ __forceinline__ void mma8(float& d0, float& d1, float& d2, float& d3,
    unsigned a0, unsigned a1, unsigned a2, unsigned a3, unsigned b0, unsigned b1)
{
    asm volatile("mma.sync.aligned.m16n8k8.row.col.f32.tf32.tf32.f32 "
        "{%0,%1,%2,%3},{%4,%5,%6,%7},{%8,%9},{%0,%1,%2,%3};"
        : "+f"(d0), "+f"(d1), "+f"(d2), "+f"(d3)
        : "r"(a0), "r"(a1), "r"(a2), "r"(a3), "r"(b0), "r"(b1));
}
__device__ __forceinline__ float dsmem_ld_f32(unsigned addr, unsigned peer) {
    unsigned r; float v;
    asm volatile("mapa.shared::cluster.u32 %0, %1, %2;" : "=r"(r) : "r"(addr), "r"(peer));
    asm volatile("ld.shared::cluster.f32 %0, [%1];" : "=f"(v) : "r"(r));
    return v;
}

#define VSWZ(nb) (((((nb)&7))<<2) | (((nb)>>2)&3))

// ---------------------------------------------------------------------------
// 3xTF32 GEMM (fp32-accurate): Y[16384,256] = X @ W. Two problems via grid.z.
// hi/lo split, 3 MMAs per fragment pair. Used for argmax-critical q,k proj.
// ---------------------------------------------------------------------------
__global__ __launch_bounds__(256) void gemm_3x_x2(
    const float* __restrict__ x0, const float* __restrict__ w0, float* __restrict__ y0,
    const float* __restrict__ x1, const float* __restrict__ w1, float* __restrict__ y1)
{
    __shared__ __align__(16) float XsH[128][20];
    __shared__ __align__(16) float XsL[128][20];
    __shared__ __align__(16) float WsH[16][136];
    __shared__ __align__(16) float WsL[16][136];

    const int t = threadIdx.x, lane = t & 31, w = t >> 5;
    const int m0 = blockIdx.y * 128, n0 = blockIdx.x * 128;
    const float* X = blockIdx.z ? x1 : x0;
    const float* W = blockIdx.z ? w1 : w0;
    float*       Y = blockIdx.z ? y1 : y0;
    const int wm = w >> 2, wn = w & 3;

    float acc[4][4][4];
    #pragma unroll
    for (int mi = 0; mi < 4; mi++)
        #pragma unroll
        for (int ni = 0; ni < 4; ni++) {
            acc[mi][ni][0] = 0.f; acc[mi][ni][1] = 0.f;
            acc[mi][ni][2] = 0.f; acc[mi][ni][3] = 0.f;
        }

    for (int kt = 0; kt < 256; kt += 16) {
        __syncthreads();
        #pragma unroll
        for (int i = 0; i < 2; i++) {
            int f = t + 256*i;
            int row = f >> 2, kq = f & 3;
            float4 xv = *(const float4*)(X + (size_t)(m0 + row)*256 + kt + kq*4);
            float vals[4] = {xv.x, xv.y, xv.z, xv.w};
            #pragma unroll
            for (int e = 0; e < 4; e++) {
                float hi = tf32f(vals[e]);
                XsH[row][kq*4 + e] = hi;
                XsL[row][kq*4 + e] = tf32f(vals[e] - hi);
            }
            int r = f >> 5, c4 = f & 31;
            float4 wv = *(const float4*)(W + (size_t)(kt + r)*256 + n0 + c4*4);
            float wvl[4] = {wv.x, wv.y, wv.z, wv.w};
            #pragma unroll
            for (int e = 0; e < 4; e++) {
                float hi = tf32f(wvl[e]);
                WsH[r][c4*4 + e] = hi;
                WsL[r][c4*4 + e] = tf32f(wvl[e] - hi);
            }
        }
        __syncthreads();
        #pragma unroll
        for (int ks = 0; ks < 2; ks++) {
            const int kk0 = ks*8;
            unsigned aH[4][4], aL[4][4], bH[4][2], bL[4][2];
            #pragma unroll
            for (int mi = 0; mi < 4; mi++) {
                const float* xp = &XsH[wm*64 + mi*16 + (lane >> 2)][kk0 + (lane & 3)];
                const float* xq = &XsL[wm*64 + mi*16 + (lane >> 2)][kk0 + (lane & 3)];
                aH[mi][0] = __float_as_uint(xp[0]);     aH[mi][1] = __float_as_uint(xp[8*20]);
                aH[mi][2] = __float_as_uint(xp[4]);     aH[mi][3] = __float_as_uint(xp[8*20+4]);
                aL[mi][0] = __float_as_uint(xq[0]);     aL[mi][1] = __float_as_uint(xq[8*20]);
                aL[mi][2] = __float_as_uint(xq[4]);     aL[mi][3] = __float_as_uint(xq[8*20+4]);
            }
            #pragma unroll
            for (int ni = 0; ni < 4; ni++) {
                const float* wp = &WsH[kk0 + (lane & 3)][wn*32 + ni*8 + (lane >> 2)];
                const float* wq = &WsL[kk0 + (lane & 3)][wn*32 + ni*8 + (lane >> 2)];
                bH[ni][0] = __float_as_uint(wp[0]); bH[ni][1] = __float_as_uint(wp[4*136]);
                bL[ni][0] = __float_as_uint(wq[0]); bL[ni][1] = __float_as_uint(wq[4*136]);
            }
            #pragma unroll
            for (int mi = 0; mi < 4; mi++)
                #pragma unroll
                for (int ni = 0; ni < 4; ni++) {
                    mma8(acc[mi][ni][0], acc[mi][ni][1], acc[mi][ni][2], acc[mi][ni][3],
                         aH[mi][0], aH[mi][1], aH[mi][2], aH[mi][3], bH[ni][0], bH[ni][1]);
                    mma8(acc[mi][ni][0], acc[mi][ni][1], acc[mi][ni][2], acc[mi][ni][3],
                         aH[mi][0], aH[mi][1], aH[mi][2], aH[mi][3], bL[ni][0], bL[ni][1]);
                    mma8(acc[mi][ni][0], acc[mi][ni][1], acc[mi][ni][2], acc[mi][ni][3],
                         aL[mi][0], aL[mi][1], aL[mi][2], aL[mi][3], bH[ni][0], bH[ni][1]);
                }
        }
    }
    #pragma unroll
    for (int mi = 0; mi < 4; mi++) {
        int row = m0 + wm*64 + mi*16 + (lane >> 2);
        #pragma unroll
        for (int ni = 0; ni < 4; ni++) {
            int col = n0 + wn*32 + ni*8 + 2*(lane & 3);
            *(float2*)(Y + (size_t)row*256 + col)     = make_float2(acc[mi][ni][0], acc[mi][ni][1]);
            *(float2*)(Y + (size_t)(row+8)*256 + col) = make_float2(acc[mi][ni][2], acc[mi][ni][3]);
        }
    }
}

// ---------------------------------------------------------------------------
// plain tf32 GEMM body (K=256). Used for v proj, final Wproj, and kh/vh (x2).
// ---------------------------------------------------------------------------
__device__ __forceinline__ void gemm_tf32_body(const float* __restrict__ X,
    const float* __restrict__ W, float* __restrict__ Y, int NC)
{
    __shared__ __align__(16) float Xs[128][36];
    __shared__ __align__(16) float Ws[32][136];

    const int t = threadIdx.x, lane = t & 31, w = t >> 5;
    const int m0 = blockIdx.y * 128, n0 = blockIdx.x * 128;
    const int wm = w >> 2, wn = w & 3;

    float acc[4][4][4];
    #pragma unroll
    for (int mi = 0; mi < 4; mi++)
        #pragma unroll
        for (int ni = 0; ni < 4; ni++) {
            acc[mi][ni][0] = 0.f; acc[mi][ni][1] = 0.f;
            acc[mi][ni][2] = 0.f; acc[mi][ni][3] = 0.f;
        }

    for (int kt = 0; kt < 256; kt += 32) {
        __syncthreads();
        #pragma unroll
        for (int i = 0; i < 4; i++) {
            int f4 = t + 256*i;
            int row = f4 >> 3, kq = f4 & 7;
            float4 xv = *(const float4*)(X + (size_t)(m0 + row)*256 + kt + kq*4);
            float* d = &Xs[row][kq*4];
            d[0] = tf32f(xv.x); d[1] = tf32f(xv.y); d[2] = tf32f(xv.z); d[3] = tf32f(xv.w);
        }
        #pragma unroll
        for (int i = 0; i < 4; i++) {
            int f4 = t + 256*i;
            int r = f4 >> 5, c4 = f4 & 31;
            float4 wv = *(const float4*)(W + (size_t)(kt + r)*NC + n0 + c4*4);
            float4 o;
            o.x = tf32f(wv.x); o.y = tf32f(wv.y); o.z = tf32f(wv.z); o.w = tf32f(wv.w);
            *(float4*)&Ws[r][c4*4] = o;
        }
        __syncthreads();
        #pragma unroll
        for (int ks = 0; ks < 4; ks++) {
            const int kk0 = ks*8;
            unsigned a[4][4], bf[4][2];
            #pragma unroll
            for (int mi = 0; mi < 4; mi++) {
                const float* xp = &Xs[wm*64 + mi*16 + (lane >> 2)][kk0 + (lane & 3)];
                a[mi][0] = __float_as_uint(xp[0]);
                a[mi][1] = __float_as_uint(xp[8*36]);
                a[mi][2] = __float_as_uint(xp[4]);
                a[mi][3] = __float_as_uint(xp[8*36 + 4]);
            }
            #pragma unroll
            for (int ni = 0; ni < 4; ni++) {
                const float* wp = &Ws[kk0 + (lane & 3)][wn*32 + ni*8 + (lane >> 2)];
                bf[ni][0] = __float_as_uint(wp[0]);
                bf[ni][1] = __float_as_uint(wp[4*136]);
            }
            #pragma unroll
            for (int mi = 0; mi < 4; mi++)
                #pragma unroll
                for (int ni = 0; ni < 4; ni++)
                    mma8(acc[mi][ni][0], acc[mi][ni][1], acc[mi][ni][2], acc[mi][ni][3],
                         a[mi][0], a[mi][1], a[mi][2], a[mi][3], bf[ni][0], bf[ni][1]);
        }
    }
    #pragma unroll
    for (int mi = 0; mi < 4; mi++) {
        int row = m0 + wm*64 + mi*16 + (lane >> 2);
        #pragma unroll
        for (int ni = 0; ni < 4; ni++) {
            int col = n0 + wn*32 + ni*8 + 2*(lane & 3);
            *(float2*)(Y + (size_t)row*NC + col)     = make_float2(acc[mi][ni][0], acc[mi][ni][1]);
            *(float2*)(Y + (size_t)(row+8)*NC + col) = make_float2(acc[mi][ni][2], acc[mi][ni][3]);
        }
    }
}

__global__ __launch_bounds__(256) void gemm_tf32_one(const float* __restrict__ X,
    const float* __restrict__ W, float* __restrict__ Y, int NC)
{
    gemm_tf32_body(X, W, Y, NC);
}

__global__ __launch_bounds__(256) void gemm_tf32_x2(
    const float* __restrict__ x0, const float* __restrict__ w0, float* __restrict__ y0,
    const float* __restrict__ x1, const float* __restrict__ w1, float* __restrict__ y1,
    int NC)
{
    const float* X = blockIdx.z ? x1 : x0;
    const float* W = blockIdx.z ? w1 : w0;
    float*       Y = blockIdx.z ? y1 : y0;
    gemm_tf32_body(X, W, Y, NC);
}

// ---------------------------------------------------------------------------
// Prep: alignment table + bitmasks, row marginals
// ---------------------------------------------------------------------------
__global__ __launch_bounds__(256) void prep_kernel(const int* __restrict__ supp_mask)
{
    int t = threadIdx.x;
    if (t < NQ*NQ) {
        int s = t / NQ, q = t % NQ;
        int prod = (2*s + 3) * (2*q + 3);
        int r = (int)(sqrtf((float)prod) + 0.5f);
        g_Ptab[t] = (r*r == prod) ? 0.f : -10000.f;
    }
    if (t < NQ) {
        unsigned m = 0;
        for (int s = 0; s < NQ; s++) {
            int prod = (2*s + 3) * (2*t + 3);
            int r = (int)(sqrtf((float)prod) + 0.5f);
            if (r*r == prod) m |= (1u << s);
        }
        g_alignbits[t] = m;
    }
    __shared__ int red[256];
    int b = t >> 6, j = t & 63;
    int cnt = 0;
    for (int i = j; i < NN; i += 64) cnt += (supp_mask[b*NN + i] == 0);
    red[t] = cnt;
    __syncthreads();
    for (int o = 32; o; o >>= 1) { if (j < o) red[t] += red[t + o]; __syncthreads(); }
    if (j == 0) {
        float nbg = (float)red[t];
        float nfg = (float)NN - nbg;
        for (int m2 = 0; m2 < NQ; m2++) g_rowm[b*NM + m2] = nfg / (float)(NQ * NN);
        g_rowm[b*NM + NQ] = nbg / (float)NN;
    }
}

// exists[b][s]: any j with valid==0 and aligned(s, sids_j) -> rowmax table
__global__ __launch_bounds__(256) void exists_kernel(const int* __restrict__ valid)
{
    __shared__ unsigned red[256];
    int b = blockIdx.x, t = threadIdx.x;
    unsigned m = 0;
    for (int j = t; j < NN; j += 256)
        if (valid[b*NN + j] == 0) m |= g_alignbits[g_sids[b*NN + j]];
    red[t] = m;
    __syncthreads();
    for (int o = 128; o; o >>= 1) { if (t < o) red[t] |= red[t + o]; __syncthreads(); }
    if (t < NQ)
        g_rowmaxtab[b*NQ + t] = ((red[0] >> t) & 1u) ? 1.0f : -9999.0f;
}

// ---------------------------------------------------------------------------
// seed + qh
// ---------------------------------------------------------------------------
__global__ __launch_bounds__(256) void seed_qh_kernel(const float* __restrict__ sv,
                                                      const float* __restrict__ Ws,
                                                      const float* __restrict__ Wqs)
{
    __shared__ float svc[CC];
    __shared__ float sd[CC];
    int bq = blockIdx.x;
    int b = bq / NQ, q = bq % NQ;
    int t = threadIdx.x;
    svc[t] = sv[((size_t)b*CC + t)*NQ + q];
    __syncthreads();
    float a = 0.f;
    #pragma unroll 8
    for (int c = 0; c < CC; c++) a += svc[c] * Ws[(size_t)c*CC + t];
    g_seed[(size_t)bq*CC + t] = a;
    sd[t] = a;
    __syncthreads();
    #pragma unroll
    for (int h = 0; h < 2; h++) {
        int d = t + 256*h;
        float a2 = 0.f;
        #pragma unroll 8
        for (int c = 0; c < CC; c++) a2 += sd[c] * Wqs[(size_t)c*DK + d];
        g_qh[(size_t)bq*DK + d] = a2;
    }
}

// ---------------------------------------------------------------------------
// logits
// ---------------------------------------------------------------------------
__global__ __launch_bounds__(256) void logits_kernel(const int* __restrict__ supp_mask)
{
    __shared__ __align__(16) float qh_s[NQ*DK];
    int b = blockIdx.y;
    int n = blockIdx.x * 256 + threadIdx.x;
    for (int i = threadIdx.x; i < NQ*DK; i += 256) qh_s[i] = g_qh[(size_t)b*NQ*DK + i];
    __syncthreads();
    const float4* kh4 = (const float4*)(g_kh + ((size_t)b*NN + n) * DK);
    float acc[NQ];
    #pragma unroll
    for (int q = 0; q < NQ; q++) acc[q] = 0.f;
    for (int c4 = 0; c4 < DK/4; c4++) {
        float4 kv = kh4[c4];
        #pragma unroll
        for (int q = 0; q < NQ; q++) {
            float4 qv = *(float4*)&qh_s[q*DK + c4*4];
            acc[q] += d4(kv, qv);
        }
    }
    const float sc = 0.044194173824159216f;
    bool masked = (supp_mask[b*NN + n] == 0);
    #pragma unroll
    for (int q = 0; q < NQ; q++)
        g_logits[((size_t)b*NQ + q)*NN + n] = masked ? -1e9f : acc[q] * sc;
}

// ---------------------------------------------------------------------------
// ctx partials + combine
// ---------------------------------------------------------------------------
__global__ __launch_bounds__(512) void ctx_part_kernel()
{
    __shared__ float ls[512];
    __shared__ float red[512];
    int q = blockIdx.x, b = blockIdx.y, c = blockIdx.z, t = threadIdx.x;
    const float* lrow = g_logits + ((size_t)b*NQ + q)*NN + c*512;
    float v = lrow[t];
    red[t] = v;
    __syncthreads();
    for (int o = 256; o; o >>= 1) { if (t < o) red[t] = fmaxf(red[t], red[t+o]); __syncthreads(); }
    float m = red[0];
    __syncthreads();
    float p = expf(v - m);
    ls[t] = p;
    red[t] = p;
    __syncthreads();
    for (int o = 256; o; o >>= 1) { if (t < o) red[t] += red[t+o]; __syncthreads(); }
    float S = red[0];
    __syncthreads();
    const float* vb = g_vh + ((size_t)b*NN + c*512)*DK;
    float a0 = 0.f, a1 = 0.f, a2 = 0.f, a3 = 0.f;
    for (int n = 0; n < 512; n += 4) {
        a0 += ls[n+0] * vb[(size_t)(n+0)*DK + t];
        a1 += ls[n+1] * vb[(size_t)(n+1)*DK + t];
        a2 += ls[n+2] * vb[(size_t)(n+2)*DK + t];
        a3 += ls[n+3] * vb[(size_t)(n+3)*DK + t];
    }
    int idx = (b*NQ + q)*8 + c;
    if (t == 0) { g_cm[idx] = m; g_cS[idx] = S; }
    g_cp[(size_t)idx*DK + t] = (a0 + a1) + (a2 + a3);
}

__global__ __launch_bounds__(512) void ctx_comb_kernel()
{
    int q = blockIdx.x, b = blockIdx.y, t = threadIdx.x;
    int base = (b*NQ + q)*8;
    float m = -INFINITY;
    #pragma unroll
    for (int c = 0; c < 8; c++) m = fmaxf(m, g_cm[base + c]);
    float S = 0.f, ctx = 0.f;
    #pragma unroll
    for (int c = 0; c < 8; c++) {
        float e = expf(g_cm[base + c] - m);
        S   += g_cS[base + c] * e;
        ctx += g_cp[(size_t)(base + c)*DK + t] * e;
    }
    g_ctx[((size_t)b*NQ + q)*DK + t] = ctx / S;
}

// ---------------------------------------------------------------------------
// prototypes
// ---------------------------------------------------------------------------
__global__ __launch_bounds__(256) void proto_kernel(const float* __restrict__ Wfc,
    const float* __restrict__ bfc, const float* __restrict__ ln_g,
    const float* __restrict__ ln_b, const float* __restrict__ Wsk,
    const float* __restrict__ Wsq)
{
    __shared__ float cs[DK];
    __shared__ float ps[CC];
    __shared__ float red[256];
    int bq = blockIdx.x, t = threadIdx.x;
    cs[t]       = g_ctx[(size_t)bq*DK + t];
    cs[t + 256] = g_ctx[(size_t)bq*DK + t + 256];
    __syncthreads();
    float pre = bfc[t] + g_seed[(size_t)bq*CC + t];
    #pragma unroll 8
    for (int k2 = 0; k2 < DK; k2++) pre += cs[k2] * Wfc[(size_t)k2*CC + t];
    red[t] = pre;
    __syncthreads();
    for (int o = 128; o; o >>= 1) { if (t < o) red[t] += red[t+o]; __syncthreads(); }
    float mu = red[0] * (1.f/256.f);
    __syncthreads();
    float dd = pre - mu;
    red[t] = dd * dd;
    __syncthreads();
    for (int o = 128; o; o >>= 1) { if (t < o) red[t] += red[t+o]; __syncthreads(); }
    float var = red[0] * (1.f/256.f);
    __syncthreads();
    float prot = dd / sqrtf(var + 1e-5f) * ln_g[t] + ln_b[t];
    ps[t] = prot;
    __syncthreads();
    float pk = 0.f, pq = 0.f;
    #pragma unroll 8
    for (int c = 0; c < CC; c++) {
        float pv = ps[c];
        pk += pv * Wsk[(size_t)c*CC + t];
        pq += pv * Wsq[(size_t)c*CC + t];
    }
    red[t] = pk * pk;
    __syncthreads();
    for (int o = 128; o; o >>= 1) { if (t < o) red[t] += red[t+o]; __syncthreads(); }
    float nk = sqrtf(red[0]);
    __syncthreads();
    red[t] = pq * pq;
    __syncthreads();
    for (int o = 128; o; o >>= 1) { if (t < o) red[t] += red[t+o]; __syncthreads(); }
    float nq2 = sqrtf(red[0]);
    g_pkn[(size_t)bq*CC + t] = pk / fmaxf(nk,  1e-12f);
    g_pqn[(size_t)bq*CC + t] = pq / fmaxf(nq2, 1e-12f);
}

// ---------------------------------------------------------------------------
// rowsim
// ---------------------------------------------------------------------------
__global__ __launch_bounds__(256) void rowsim_kernel(const int* __restrict__ supp_mask)
{
    __shared__ __align__(16) float pkn_s[NQ*CC];
    __shared__ __align__(16) float pqn_s[NQ*CC];
    int t = threadIdx.x, lane = t & 31, wid = t >> 5;
    int g = blockIdx.x * 8 + wid;
    int b = g >> 12;
    for (int i = t; i < NQ*CC; i += 256) {
        pkn_s[i] = g_pkn[(size_t)b*NQ*CC + i];
        pqn_s[i] = g_pqn[(size_t)b*NQ*CC + i];
    }
    __syncthreads();
    const float* qrow = g_qs + (size_t)g*CC;
    const float* krow = g_kk + (size_t)g*CC;
    float4 q0 = *(const float4*)(qrow + lane*4);
    float4 q1 = *(const float4*)(qrow + 128 + lane*4);
    float4 k0 = *(const float4*)(krow + lane*4);
    float4 k1 = *(const float4*)(krow + 128 + lane*4);
    float rnq = 1.f / fmaxf(sqrtf(wsum(d4(q0,q0) + d4(q1,q1))), 1e-12f);
    float rnk = 1.f / fmaxf(sqrtf(wsum(d4(k0,k0) + d4(k1,k1))), 1e-12f);
    float myq2p = 0.f, myK = 0.f;
    float best = -INFINITY; int bk = 0;
    #pragma unroll
    for (int k2 = 0; k2 < NQ; k2++) {
        float4 p0 = *(float4*)&pkn_s[k2*CC + lane*4];
        float4 p1 = *(float4*)&pkn_s[k2*CC + 128 + lane*4];
        float val = wsum(d4(q0,p0) + d4(q1,p1)) * rnq;
        if (val > best) { best = val; bk = k2; }
        if (lane == k2) myq2p = val;
        float4 r0 = *(float4*)&pqn_s[k2*CC + lane*4];
        float4 r1 = *(float4*)&pqn_s[k2*CC + 128 + lane*4];
        float a = wsum(d4(k0,r0) + d4(k1,r1)) * rnk;
        if (lane == k2) myK = expf(20.f * (a - 1.f));
    }
    if (lane < NQ) {
        g_q2p[(size_t)g*NQ + lane]  = myq2p;
        g_Kmat[(size_t)g*NM + lane] = myK;
    }
    if (lane == NQ)
        g_Kmat[(size_t)g*NM + NQ] = (supp_mask[g] > 0) ? expf(-40.f) : 1.f;
    if (lane == 0) g_sidq[g] = bk;
}

// ---------------------------------------------------------------------------
// Sinkhorn: 2-CTA clusters, DSMEM partial exchange (proven in round 14).
// ---------------------------------------------------------------------------
__global__ __launch_bounds__(512) __cluster_dims__(2,1,1) void sinkhorn_kernel()
{
    __shared__ float sred[16*NM];
    __shared__ float v_s[NM];
    __shared__ float part_s[2][NM];
    int t = threadIdx.x, lane = t & 31, wid = t >> 5;
    int b = blockIdx.x >> 1;
    unsigned rank = blockIdx.x & 1;
    unsigned part_base = (unsigned)__cvta_generic_to_shared(&part_s[0][0]);

    float Kl[4][NM];
    int rowg[4];
    #pragma unroll
    for (int i = 0; i < 4; i++) {
        int n = (int)rank*2048 + i*512 + t;
        rowg[i] = b*NN + n;
        #pragma unroll
        for (int j = 0; j < NM; j++) Kl[i][j] = g_Kmat[(size_t)rowg[i]*NM + j];
    }
    float u[4] = {1.f/NN, 1.f/NN, 1.f/NN, 1.f/NN};

    for (int iter = 0; iter < 100; iter++) {
        #pragma unroll
        for (int j = 0; j < NM; j++) {
            float x = Kl[0][j]*u[0] + Kl[1][j]*u[1] + Kl[2][j]*u[2] + Kl[3][j]*u[3];
            x = wsum(x);
            if (lane == 0) sred[wid*NM + j] = x;
        }
        __syncthreads();
        if (t < NM) {
            float bp = 0.f;
            #pragma unroll
            for (int w2 = 0; w2 < 16; w2++) bp += sred[w2*NM + t];
            part_s[iter & 1][t] = bp;
        }
        asm volatile("barrier.cluster.arrive.aligned;" ::: "memory");
        asm volatile("barrier.cluster.wait.aligned;" ::: "memory");
        if (t < NM) {
            float own  = part_s[iter & 1][t];
            float peer = dsmem_ld_f32(part_base + ((iter & 1)*NM + t)*4u, rank ^ 1u);
            float h0 = rank == 0 ? own : peer;
            float h1 = rank == 0 ? peer : own;
            v_s[t] = g_rowm[b*NM + t] / ((h0 + h1) + 1e-16f);
        }
        __syncthreads();
        #pragma unroll
        for (int i = 0; i < 4; i++) {
            float dsum = 0.f;
            #pragma unroll
            for (int j = 0; j < NM; j++) dsum += Kl[i][j]*v_s[j];
            u[i] = (1.f/NN) / (dsum + 1e-16f);
        }
    }
    asm volatile("barrier.cluster.arrive.aligned;" ::: "memory");
    asm volatile("barrier.cluster.wait.aligned;" ::: "memory");

    #pragma unroll
    for (int i = 0; i < 4; i++) {
        float best = -INFINITY; int bk = 0;
        #pragma unroll
        for (int j = 0; j < NQ; j++) {
            float tv = fmaxf(u[i]*Kl[i][j]*v_s[j]*(float)NN, 0.f);
            g_s2p[(size_t)rowg[i]*NQ + j] = tv;
            if (tv > best) { best = tv; bk = j; }
        }
        g_sids[rowg[i]] = bk;
    }
}

// ---------------------------------------------------------------------------
// Flash v2: fixed per-row max (scores provably <= 1), no online rescale,
// lane-local l accumulation, fragment-major swizzled V (LDS.64 b-frags).
// ---------------------------------------------------------------------------
__global__ __launch_bounds__(256, 2) void flash_mma(const int* __restrict__ valid)
{
    __shared__ uint4 Qf[8*4*32];
    __shared__ uint2 Kf[4*4*32];
    __shared__ uint2 Vf[4*16*32];

    const int t = threadIdx.x, lane = t & 31, w = t >> 5;
    const int b = blockIdx.y;
    const int i0 = (blockIdx.x >> 1) * 128;
    const int cbase = (blockIdx.x & 1) * 128;

    for (int idx = t; idx < 128*32; idx += 256) {
        int q = idx >> 5, c = idx & 31;
        int gi = b*NN + i0 + q;
        float val;
        if (c < 14)       val = g_q2p[(size_t)gi*NQ + c];
        else if (c < 28)  val = (g_sidq[gi] == c - 14) ? 1.f : 0.f;
        else              val = (c == 28) ? 1.f : 0.f;
        int ww = q >> 4, qr = q & 15, ks = c >> 3, ck = c & 7;
        int ln = ((qr & 7) << 2) | (ck & 3);
        int rg = ((ck >> 2) << 1) | (qr >> 3);
        ((unsigned*)&Qf[(ww*4 + ks)*32 + ln])[rg] = tf32r(val);
    }
    __syncthreads();
    uint4 aS[4];
    #pragma unroll
    for (int ks = 0; ks < 4; ks++) aS[ks] = Qf[(w*4 + ks)*32 + lane];

    const int row_lo = i0 + w*16 + (lane >> 2);
    const float M_lo = g_rowmaxtab[b*NQ + g_sidq[b*NN + row_lo]];
    const float M_hi = g_rowmaxtab[b*NQ + g_sidq[b*NN + row_lo + 8]];

    float acc[16][4];
    #pragma unroll
    for (int nb = 0; nb < 16; nb++) {
        acc[nb][0] = 0.f; acc[nb][1] = 0.f; acc[nb][2] = 0.f; acc[nb][3] = 0.f;
    }
    float l_lo = 0.f, l_hi = 0.f;

    for (int kt = 0; kt < NN/32; kt++) {
        int k0 = kt * 32;
        __syncthreads();
        // Kext fragments
        for (int idx = t; idx < 32*32; idx += 256) {
            int jl = idx >> 5, c = idx & 31;
            int gj = b*NN + k0 + jl;
            float val;
            if (c < 14)       val = g_s2p[(size_t)gj*NQ + c];
            else if (c < 28)  val = g_Ptab[(c - 14)*NQ + g_sids[gj]];
            else              val = (c == 28) ? -10000.f * (float)valid[gj] : 0.f;
            int ks = c >> 3, ck = c & 7;
            int ln = ((jl & 7) << 2) | (ck & 3);
            ((unsigned*)&Kf[((jl >> 3)*4 + ks)*32 + ln])[ck >> 2] = tf32r(val);
        }
        // V fragments, swizzled frag-major
        #pragma unroll
        for (int i = 0; i < 4; i++) {
            int kr = w + 8*i;
            float4 v4 = *(const float4*)(g_vv + ((size_t)(b*NN + k0 + kr))*CC + cbase + lane*4);
            int kb = kr >> 3, reg = (kr >> 2) & 1, krow = kr & 3;
            float vals[4] = {v4.x, v4.y, v4.z, v4.w};
            #pragma unroll
            for (int e = 0; e < 4; e++) {
                int n  = lane*4 + e;
                int nb = n >> 3, nw = n & 7;
                int ln = ((nw << 2) | krow) ^ VSWZ(nb);
                ((unsigned*)&Vf[(kb*16 + nb)*32 + ln])[reg] = tf32r(vals[e]);
            }
        }
        __syncthreads();

        // S = Qext . Kext^T
        float s0[4], s1[4], s2[4], s3[4];
        #pragma unroll
        for (int nb = 0; nb < 4; nb++) {
            float c0 = 0.f, c1 = 0.f, c2 = 0.f, c3 = 0.f;
            #pragma unroll
            for (int ks = 0; ks < 4; ks++) {
                uint2 bv = Kf[(nb*4 + ks)*32 + lane];
                mma8(c0, c1, c2, c3, aS[ks].x, aS[ks].y, aS[ks].z, aS[ks].w, bv.x, bv.y);
            }
            s0[nb] = c0; s1[nb] = c1; s2[nb] = c2; s3[nb] = c3;
        }

        // p = exp(s - M); lane-local l accumulation (no shuffles, no rescale)
        #pragma unroll
        for (int nb = 0; nb < 4; nb++) {
            s0[nb] = __expf(s0[nb] - M_lo);
            s1[nb] = __expf(s1[nb] - M_lo);
            s2[nb] = __expf(s2[nb] - M_hi);
            s3[nb] = __expf(s3[nb] - M_hi);
            l_lo += s0[nb] + s1[nb];
            l_hi += s2[nb] + s3[nb];
        }

        // P (C-frag) -> A-frags for all 4 k-groups
        const int src0 = (lane & ~3) | ((lane & 3) >> 1);
        const int src2 = src0 + 2;
        const bool odd = lane & 1;
        unsigned pa[4][4];
        #pragma unroll
        for (int kb = 0; kb < 4; kb++) {
            unsigned p0 = tf32r(s0[kb]), p1 = tf32r(s1[kb]);
            unsigned p2 = tf32r(s2[kb]), p3 = tf32r(s3[kb]);
            unsigned q00 = __shfl_sync(0xffffffffu, p0, src0);
            unsigned q01 = __shfl_sync(0xffffffffu, p1, src0);
            unsigned q20 = __shfl_sync(0xffffffffu, p0, src2);
            unsigned q21 = __shfl_sync(0xffffffffu, p1, src2);
            unsigned q10 = __shfl_sync(0xffffffffu, p2, src0);
            unsigned q11 = __shfl_sync(0xffffffffu, p3, src0);
            unsigned q30 = __shfl_sync(0xffffffffu, p2, src2);
            unsigned q31 = __shfl_sync(0xffffffffu, p3, src2);
            pa[kb][0] = odd ? q01 : q00;
            pa[kb][1] = odd ? q11 : q10;
            pa[kb][2] = odd ? q21 : q20;
            pa[kb][3] = odd ? q31 : q30;
        }
        // PV: nb-outer so the swizzled lane index is computed once per nb
        #pragma unroll
        for (int nb = 0; nb < 16; nb++) {
            const uint2* vx = &Vf[nb*32 + (lane ^ VSWZ(nb))];
            #pragma unroll
            for (int kb = 0; kb < 4; kb++) {
                uint2 bv = vx[kb*16*32];
                mma8(acc[nb][0], acc[nb][1], acc[nb][2], acc[nb][3],
                     pa[kb][0], pa[kb][1], pa[kb][2], pa[kb][3], bv.x, bv.y);
            }
        }
    }

    // final l reduction over the quad, then epilogue
    l_lo += __shfl_xor_sync(0xffffffffu, l_lo, 1);
    l_lo += __shfl_xor_sync(0xffffffffu, l_lo, 2);
    l_hi += __shfl_xor_sync(0xffffffffu, l_hi, 1);
    l_hi += __shfl_xor_sync(0xffffffffu, l_hi, 2);
    float il_lo = 1.f / l_lo, il_hi = 1.f / l_hi;
    int col0 = cbase + 2*(lane & 3);
    float* out_lo = g_xattn + ((size_t)b*NN + row_lo)*CC + col0;
    float* out_hi = out_lo + 8*CC;
    #pragma unroll
    for (int nb = 0; nb < 16; nb++) {
        *(float2*)(out_lo + nb*8) = make_float2(acc[nb][0]*il_lo, acc[nb][1]*il_lo);
        *(float2*)(out_hi + nb*8) = make_float2(acc[nb][2]*il_hi, acc[nb][3]*il_hi);
    }
}

// ---------------------------------------------------------------------------
// Launch
// ---------------------------------------------------------------------------
extern "C" void kernel_launch(void* const* d_in, const int* in_sizes, int n_in,
                              void* d_out, int out_size)
{
    (void)in_sizes; (void)n_in; (void)out_size;
    const float* q      = (const float*)d_in[0];
    const float* k      = (const float*)d_in[1];
    const float* v      = (const float*)d_in[2];
    const float* sv     = (const float*)d_in[3];
    const int*   svalid = (const int*)d_in[4];
    const int*   smask  = (const int*)d_in[5];
    const float* Wq     = (const float*)d_in[6];
    const float* Wk     = (const float*)d_in[7];
    const float* Wv     = (const float*)d_in[8];
    const float* Ws     = (const float*)d_in[9];
    const float* Wsq    = (const float*)d_in[10];
    const float* Wsk    = (const float*)d_in[11];
    const float* Wproj  = (const float*)d_in[12];
    const float* Wqs    = (const float*)d_in[13];
    const float* Wks    = (const float*)d_in[14];
    const float* Wvs    = (const float*)d_in[15];
    const float* Wfc    = (const float*)d_in[16];
    const float* bfc    = (const float*)d_in[17];
    const float* lng    = (const float*)d_in[18];
    const float* lnb    = (const float*)d_in[19];
    float* out = (float*)d_out;

    float *p_qs, *p_kk, *p_vv, *p_kh, *p_vh, *p_xa;
    cudaGetSymbolAddress((void**)&p_qs, g_qs);
    cudaGetSymbolAddress((void**)&p_kk, g_kk);
    cudaGetSymbolAddress((void**)&p_vv, g_vv);
    cudaGetSymbolAddress((void**)&p_kh, g_kh);
    cudaGetSymbolAddress((void**)&p_vh, g_vh);
    cudaGetSymbolAddress((void**)&p_xa, g_xattn);

    prep_kernel<<<1, 256>>>(smask);
    gemm_3x_x2<<<dim3(2, 128, 2), 256>>>(q, Wq, p_qs, k, Wk, p_kk);
    gemm_tf32_one<<<dim3(2, 128), 256>>>(v, Wv, p_vv, 256);
    seed_qh_kernel<<<BB*NQ, 256>>>(sv, Ws, Wqs);
    gemm_tf32_x2<<<dim3(4, 128, 2), 256>>>(p_kk, Wks, p_kh, p_vv, Wvs, p_vh, 512);
    logits_kernel<<<dim3(NN/256, BB), 256>>>(smask);
    ctx_part_kernel<<<dim3(NQ, BB, 8), 512>>>();
    ctx_comb_kernel<<<dim3(NQ, BB), 512>>>();
    proto_kernel<<<BB*NQ, 256>>>(Wfc, bfc, lng, lnb, Wsk, Wsq);
    rowsim_kernel<<<BB*NN/8, 256>>>(smask);
    sinkhorn_kernel<<<8, 512>>>();
    exists_kernel<<<BB, 256>>>(svalid);
    flash_mma<<<dim3(64, BB), 256>>>(svalid);
    gemm_tf32_one<<<dim3(2, 128), 256>>>(p_xa, Wproj, out, 256);
}

// round 16
// speedup vs baseline: 2.5164x; 1.2180x over previous
#include <cuda_runtime.h>
#include <math.h>

#define BB 4
#define NN 4096
#define CC 256
#define NQ 14
#define DK 512
#define NM 15

// ---------------- scratch (device globals; allocation-free) ----------------
__device__ float g_qs[BB*NN*CC];
__device__ float g_kk[BB*NN*CC];
__device__ float g_vv[BB*NN*CC];
__device__ float g_kh[BB*NN*DK];
__device__ float g_vh[BB*NN*DK];
__device__ float g_seed[BB*NQ*CC];
__device__ float g_qh[BB*NQ*DK];
__device__ float g_logits[BB*NQ*NN];
__device__ float g_cm[BB*NQ*8];
__device__ float g_cS[BB*NQ*8];
__device__ float g_cp[BB*NQ*8*DK];
__device__ float g_pkn[BB*NQ*CC];
__device__ float g_pqn[BB*NQ*CC];
__device__ float g_q2p[BB*NN*NQ];
__device__ int   g_sidq[BB*NN];
__device__ float g_Kmat[BB*NN*NM];
__device__ float g_s2p[BB*NN*NQ];
__device__ int   g_sids[BB*NN];
__device__ float g_rowm[BB*NM];
__device__ float g_Ptab[NQ*NQ];
__device__ unsigned g_alignbits[NQ];
__device__ unsigned g_maskbits[BB];
__device__ uint2 g_kextf[BB*128*512];   // Kext in flash fragment order, per (b, key-tile)
__device__ float g_xattn[BB*NN*CC];

__device__ __forceinline__ float d4(float4 a, float4 b) {
    return a.x*b.x + a.y*b.y + a.z*b.z + a.w*b.w;
}
__device__ __forceinline__ float wsum(float v) {
    #pragma unroll
    for (int o = 16; o; o >>= 1) v += __shfl_xor_sync(0xffffffffu, v, o);
    return v;
}
__device__ __forceinline__ unsigned tf32r(float x) {
    unsigned y; asm("cvt.rna.tf32.f32 %0, %1;" : "=r"(y) : "f"(x)); return y;
}
__device__ __forceinline__ float tf32f(float x) { return __uint_as_float(tf32r(x)); }
__device__ __forceinline__ void mma8(float& d0, float& d1, float& d2, float& d3,
    unsigned a0, unsigned a1, unsigned a2, unsigned a3, unsigned b0, unsigned b1)
{
    asm volatile("mma.sync.aligned.m16n8k8.row.col.f32.tf32.tf32.f32 "
        "{%0,%1,%2,%3},{%4,%5,%6,%7},{%8,%9},{%0,%1,%2,%3};"
        : "+f"(d0), "+f"(d1), "+f"(d2), "+f"(d3)
        : "r"(a0), "r"(a1), "r"(a2), "r"(a3), "r"(b0), "r"(b1));
}
__device__ __forceinline__ float dsmem_ld_f32(unsigned addr, unsigned peer) {
    unsigned r; float v;
    asm volatile("mapa.shared::cluster.u32 %0, %1, %2;" : "=r"(r) : "r"(addr), "r"(peer));
    asm volatile("ld.shared::cluster.f32 %0, [%1];" : "=f"(v) : "r"(r));
    return v;
}

#define VSWZ(nb) (((((nb)&7))<<2) | (((nb)>>2)&3))

// ---------------------------------------------------------------------------
// 3xTF32 GEMM (fp32-accurate) for argmax-critical q,k projections.
// ---------------------------------------------------------------------------
__global__ __launch_bounds__(256) void gemm_3x_x2(
    const float* __restrict__ x0, const float* __restrict__ w0, float* __restrict__ y0,
    const float* __restrict__ x1, const float* __restrict__ w1, float* __restrict__ y1)
{
    __shared__ __align__(16) float XsH[128][20];
    __shared__ __align__(16) float XsL[128][20];
    __shared__ __align__(16) float WsH[16][136];
    __shared__ __align__(16) float WsL[16][136];

    const int t = threadIdx.x, lane = t & 31, w = t >> 5;
    const int m0 = blockIdx.y * 128, n0 = blockIdx.x * 128;
    const float* X = blockIdx.z ? x1 : x0;
    const float* W = blockIdx.z ? w1 : w0;
    float*       Y = blockIdx.z ? y1 : y0;
    const int wm = w >> 2, wn = w & 3;

    float acc[4][4][4];
    #pragma unroll
    for (int mi = 0; mi < 4; mi++)
        #pragma unroll
        for (int ni = 0; ni < 4; ni++) {
            acc[mi][ni][0] = 0.f; acc[mi][ni][1] = 0.f;
            acc[mi][ni][2] = 0.f; acc[mi][ni][3] = 0.f;
        }

    for (int kt = 0; kt < 256; kt += 16) {
        __syncthreads();
        #pragma unroll
        for (int i = 0; i < 2; i++) {
            int f = t + 256*i;
            int row = f >> 2, kq = f & 3;
            float4 xv = *(const float4*)(X + (size_t)(m0 + row)*256 + kt + kq*4);
            float vals[4] = {xv.x, xv.y, xv.z, xv.w};
            #pragma unroll
            for (int e = 0; e < 4; e++) {
                float hi = tf32f(vals[e]);
                XsH[row][kq*4 + e] = hi;
                XsL[row][kq*4 + e] = tf32f(vals[e] - hi);
            }
            int r = f >> 5, c4 = f & 31;
            float4 wv = *(const float4*)(W + (size_t)(kt + r)*256 + n0 + c4*4);
            float wvl[4] = {wv.x, wv.y, wv.z, wv.w};
            #pragma unroll
            for (int e = 0; e < 4; e++) {
                float hi = tf32f(wvl[e]);
                WsH[r][c4*4 + e] = hi;
                WsL[r][c4*4 + e] = tf32f(wvl[e] - hi);
            }
        }
        __syncthreads();
        #pragma unroll
        for (int ks = 0; ks < 2; ks++) {
            const int kk0 = ks*8;
            unsigned aH[4][4], aL[4][4], bH[4][2], bL[4][2];
            #pragma unroll
            for (int mi = 0; mi < 4; mi++) {
                const float* xp = &XsH[wm*64 + mi*16 + (lane >> 2)][kk0 + (lane & 3)];
                const float* xq = &XsL[wm*64 + mi*16 + (lane >> 2)][kk0 + (lane & 3)];
                aH[mi][0] = __float_as_uint(xp[0]);     aH[mi][1] = __float_as_uint(xp[8*20]);
                aH[mi][2] = __float_as_uint(xp[4]);     aH[mi][3] = __float_as_uint(xp[8*20+4]);
                aL[mi][0] = __float_as_uint(xq[0]);     aL[mi][1] = __float_as_uint(xq[8*20]);
                aL[mi][2] = __float_as_uint(xq[4]);     aL[mi][3] = __float_as_uint(xq[8*20+4]);
            }
            #pragma unroll
            for (int ni = 0; ni < 4; ni++) {
                const float* wp = &WsH[kk0 + (lane & 3)][wn*32 + ni*8 + (lane >> 2)];
                const float* wq = &WsL[kk0 + (lane & 3)][wn*32 + ni*8 + (lane >> 2)];
                bH[ni][0] = __float_as_uint(wp[0]); bH[ni][1] = __float_as_uint(wp[4*136]);
                bL[ni][0] = __float_as_uint(wq[0]); bL[ni][1] = __float_as_uint(wq[4*136]);
            }
            #pragma unroll
            for (int mi = 0; mi < 4; mi++)
                #pragma unroll
                for (int ni = 0; ni < 4; ni++) {
                    mma8(acc[mi][ni][0], acc[mi][ni][1], acc[mi][ni][2], acc[mi][ni][3],
                         aH[mi][0], aH[mi][1], aH[mi][2], aH[mi][3], bH[ni][0], bH[ni][1]);
                    mma8(acc[mi][ni][0], acc[mi][ni][1], acc[mi][ni][2], acc[mi][ni][3],
                         aH[mi][0], aH[mi][1], aH[mi][2], aH[mi][3], bL[ni][0], bL[ni][1]);
                    mma8(acc[mi][ni][0], acc[mi][ni][1], acc[mi][ni][2], acc[mi][ni][3],
                         aL[mi][0], aL[mi][1], aL[mi][2], aL[mi][3], bH[ni][0], bH[ni][1]);
                }
        }
    }
    #pragma unroll
    for (int mi = 0; mi < 4; mi++) {
        int row = m0 + wm*64 + mi*16 + (lane >> 2);
        #pragma unroll
        for (int ni = 0; ni < 4; ni++) {
            int col = n0 + wn*32 + ni*8 + 2*(lane & 3);
            *(float2*)(Y + (size_t)row*256 + col)     = make_float2(acc[mi][ni][0], acc[mi][ni][1]);
            *(float2*)(Y + (size_t)(row+8)*256 + col) = make_float2(acc[mi][ni][2], acc[mi][ni][3]);
        }
    }
}

// ---------------------------------------------------------------------------
// plain tf32 GEMM body (K=256)
// ---------------------------------------------------------------------------
__device__ __forceinline__ void gemm_tf32_body(const float* __restrict__ X,
    const float* __restrict__ W, float* __restrict__ Y, int NC)
{
    __shared__ __align__(16) float Xs[128][36];
    __shared__ __align__(16) float Ws[32][136];

    const int t = threadIdx.x, lane = t & 31, w = t >> 5;
    const int m0 = blockIdx.y * 128, n0 = blockIdx.x * 128;
    const int wm = w >> 2, wn = w & 3;

    float acc[4][4][4];
    #pragma unroll
    for (int mi = 0; mi < 4; mi++)
        #pragma unroll
        for (int ni = 0; ni < 4; ni++) {
            acc[mi][ni][0] = 0.f; acc[mi][ni][1] = 0.f;
            acc[mi][ni][2] = 0.f; acc[mi][ni][3] = 0.f;
        }

    for (int kt = 0; kt < 256; kt += 32) {
        __syncthreads();
        #pragma unroll
        for (int i = 0; i < 4; i++) {
            int f4 = t + 256*i;
            int row = f4 >> 3, kq = f4 & 7;
            float4 xv = *(const float4*)(X + (size_t)(m0 + row)*256 + kt + kq*4);
            float* d = &Xs[row][kq*4];
            d[0] = tf32f(xv.x); d[1] = tf32f(xv.y); d[2] = tf32f(xv.z); d[3] = tf32f(xv.w);
        }
        #pragma unroll
        for (int i = 0; i < 4; i++) {
            int f4 = t + 256*i;
            int r = f4 >> 5, c4 = f4 & 31;
            float4 wv = *(const float4*)(W + (size_t)(kt + r)*NC + n0 + c4*4);
            float4 o;
            o.x = tf32f(wv.x); o.y = tf32f(wv.y); o.z = tf32f(wv.z); o.w = tf32f(wv.w);
            *(float4*)&Ws[r][c4*4] = o;
        }
        __syncthreads();
        #pragma unroll
        for (int ks = 0; ks < 4; ks++) {
            const int kk0 = ks*8;
            unsigned a[4][4], bf[4][2];
            #pragma unroll
            for (int mi = 0; mi < 4; mi++) {
                const float* xp = &Xs[wm*64 + mi*16 + (lane >> 2)][kk0 + (lane & 3)];
                a[mi][0] = __float_as_uint(xp[0]);
                a[mi][1] = __float_as_uint(xp[8*36]);
                a[mi][2] = __float_as_uint(xp[4]);
                a[mi][3] = __float_as_uint(xp[8*36 + 4]);
            }
            #pragma unroll
            for (int ni = 0; ni < 4; ni++) {
                const float* wp = &Ws[kk0 + (lane & 3)][wn*32 + ni*8 + (lane >> 2)];
                bf[ni][0] = __float_as_uint(wp[0]);
                bf[ni][1] = __float_as_uint(wp[4*136]);
            }
            #pragma unroll
            for (int mi = 0; mi < 4; mi++)
                #pragma unroll
                for (int ni = 0; ni < 4; ni++)
                    mma8(acc[mi][ni][0], acc[mi][ni][1], acc[mi][ni][2], acc[mi][ni][3],
                         a[mi][0], a[mi][1], a[mi][2], a[mi][3], bf[ni][0], bf[ni][1]);
        }
    }
    #pragma unroll
    for (int mi = 0; mi < 4; mi++) {
        int row = m0 + wm*64 + mi*16 + (lane >> 2);
        #pragma unroll
        for (int ni = 0; ni < 4; ni++) {
            int col = n0 + wn*32 + ni*8 + 2*(lane & 3);
            *(float2*)(Y + (size_t)row*NC + col)     = make_float2(acc[mi][ni][0], acc[mi][ni][1]);
            *(float2*)(Y + (size_t)(row+8)*NC + col) = make_float2(acc[mi][ni][2], acc[mi][ni][3]);
        }
    }
}

__global__ __launch_bounds__(256) void gemm_tf32_one(const float* __restrict__ X,
    const float* __restrict__ W, float* __restrict__ Y, int NC)
{
    gemm_tf32_body(X, W, Y, NC);
}

__global__ __launch_bounds__(256) void gemm_tf32_x2(
    const float* __restrict__ x0, const float* __restrict__ w0, float* __restrict__ y0,
    const float* __restrict__ x1, const float* __restrict__ w1, float* __restrict__ y1,
    int NC)
{
    const float* X = blockIdx.z ? x1 : x0;
    const float* W = blockIdx.z ? w1 : w0;
    float*       Y = blockIdx.z ? y1 : y0;
    gemm_tf32_body(X, W, Y, NC);
}

// ---------------------------------------------------------------------------
// Prep: alignment table + bitmasks, row marginals, zero maskbits
// ---------------------------------------------------------------------------
__global__ __launch_bounds__(256) void prep_kernel(const int* __restrict__ supp_mask)
{
    int t = threadIdx.x;
    if (t < BB) g_maskbits[t] = 0u;
    if (t < NQ*NQ) {
        int s = t / NQ, q = t % NQ;
        int prod = (2*s + 3) * (2*q + 3);
        int r = (int)(sqrtf((float)prod) + 0.5f);
        g_Ptab[t] = (r*r == prod) ? 0.f : -10000.f;
    }
    if (t < NQ) {
        unsigned m = 0;
        for (int s = 0; s < NQ; s++) {
            int prod = (2*s + 3) * (2*t + 3);
            int r = (int)(sqrtf((float)prod) + 0.5f);
            if (r*r == prod) m |= (1u << s);
        }
        g_alignbits[t] = m;
    }
    __shared__ int red[256];
    int b = t >> 6, j = t & 63;
    int cnt = 0;
    for (int i = j; i < NN; i += 64) cnt += (supp_mask[b*NN + i] == 0);
    red[t] = cnt;
    __syncthreads();
    for (int o = 32; o; o >>= 1) { if (j < o) red[t] += red[t + o]; __syncthreads(); }
    if (j == 0) {
        float nbg = (float)red[t];
        float nfg = (float)NN - nbg;
        for (int m2 = 0; m2 < NQ; m2++) g_rowm[b*NM + m2] = nfg / (float)(NQ * NN);
        g_rowm[b*NM + NQ] = nbg / (float)NN;
    }
}

// ---------------------------------------------------------------------------
// seed + qh, split-k (1024 threads): chain /4, 4x MLP
// ---------------------------------------------------------------------------
__global__ __launch_bounds__(1024) void seed_qh_kernel(const float* __restrict__ sv,
                                                       const float* __restrict__ Ws,
                                                       const float* __restrict__ Wqs)
{
    __shared__ float svc[CC];
    __shared__ float sd[CC];
    __shared__ float part[1024];
    int bq = blockIdx.x;
    int b = bq / NQ, q = bq % NQ;
    int t = threadIdx.x;
    if (t < CC) svc[t] = sv[((size_t)b*CC + t)*NQ + q];
    __syncthreads();
    {
        int d = t & 255, ch = t >> 8;           // 4 chunks of 64
        const float* wp = Ws + (size_t)(ch*64)*CC + d;
        float a = 0.f;
        #pragma unroll 16
        for (int c = 0; c < 64; c++) a += svc[ch*64 + c] * wp[(size_t)c*CC];
        part[t] = a;
    }
    __syncthreads();
    if (t < CC) {
        float s = (part[t] + part[t+256]) + (part[t+512] + part[t+768]);
        g_seed[(size_t)bq*CC + t] = s;
        sd[t] = s;
    }
    __syncthreads();
    {
        int d = t & 511, ch = t >> 9;           // 2 chunks of 128
        const float* wp = Wqs + (size_t)(ch*128)*DK + d;
        float a = 0.f;
        #pragma unroll 16
        for (int c = 0; c < 128; c++) a += sd[ch*128 + c] * wp[(size_t)c*DK];
        part[t] = a;
    }
    __syncthreads();
    if (t < 512) g_qh[(size_t)bq*DK + t] = part[t] + part[t+512];
}

// ---------------------------------------------------------------------------
// logits: 128 blocks x 128 threads (2x SM coverage vs r15)
// ---------------------------------------------------------------------------
__global__ __launch_bounds__(128) void logits_kernel(const int* __restrict__ supp_mask)
{
    __shared__ __align__(16) float qh_s[NQ*DK];
    int b = blockIdx.y;
    int n = blockIdx.x * 128 + threadIdx.x;
    for (int i = threadIdx.x; i < NQ*DK; i += 128) qh_s[i] = g_qh[(size_t)b*NQ*DK + i];
    __syncthreads();
    const float4* kh4 = (const float4*)(g_kh + ((size_t)b*NN + n) * DK);
    float acc[NQ];
    #pragma unroll
    for (int q = 0; q < NQ; q++) acc[q] = 0.f;
    for (int c4 = 0; c4 < DK/4; c4++) {
        float4 kv = kh4[c4];
        #pragma unroll
        for (int q = 0; q < NQ; q++) {
            float4 qv = *(float4*)&qh_s[q*DK + c4*4];
            acc[q] += d4(kv, qv);
        }
    }
    const float sc = 0.044194173824159216f;
    bool masked = (supp_mask[b*NN + n] == 0);
    #pragma unroll
    for (int q = 0; q < NQ; q++)
        g_logits[((size_t)b*NQ + q)*NN + n] = masked ? -1e9f : acc[q] * sc;
}

// ---------------------------------------------------------------------------
// ctx partials (combine folded into proto)
// ---------------------------------------------------------------------------
__global__ __launch_bounds__(512) void ctx_part_kernel()
{
    __shared__ float ls[512];
    __shared__ float red[512];
    int q = blockIdx.x, b = blockIdx.y, c = blockIdx.z, t = threadIdx.x;
    const float* lrow = g_logits + ((size_t)b*NQ + q)*NN + c*512;
    float v = lrow[t];
    red[t] = v;
    __syncthreads();
    for (int o = 256; o; o >>= 1) { if (t < o) red[t] = fmaxf(red[t], red[t+o]); __syncthreads(); }
    float m = red[0];
    __syncthreads();
    float p = expf(v - m);
    ls[t] = p;
    red[t] = p;
    __syncthreads();
    for (int o = 256; o; o >>= 1) { if (t < o) red[t] += red[t+o]; __syncthreads(); }
    float S = red[0];
    __syncthreads();
    const float* vb = g_vh + ((size_t)b*NN + c*512)*DK;
    float a0 = 0.f, a1 = 0.f, a2 = 0.f, a3 = 0.f;
    for (int n = 0; n < 512; n += 4) {
        a0 += ls[n+0] * vb[(size_t)(n+0)*DK + t];
        a1 += ls[n+1] * vb[(size_t)(n+1)*DK + t];
        a2 += ls[n+2] * vb[(size_t)(n+2)*DK + t];
        a3 += ls[n+3] * vb[(size_t)(n+3)*DK + t];
    }
    int idx = (b*NQ + q)*8 + c;
    if (t == 0) { g_cm[idx] = m; g_cS[idx] = S; }
    g_cp[(size_t)idx*DK + t] = (a0 + a1) + (a2 + a3);
}

// ---------------------------------------------------------------------------
// prototypes (with fused ctx combine)
// ---------------------------------------------------------------------------
__global__ __launch_bounds__(256) void proto_kernel(const float* __restrict__ Wfc,
    const float* __restrict__ bfc, const float* __restrict__ ln_g,
    const float* __restrict__ ln_b, const float* __restrict__ Wsk,
    const float* __restrict__ Wsq)
{
    __shared__ float cs[DK];
    __shared__ float ps[CC];
    __shared__ float red[256];
    int bq = blockIdx.x, t = threadIdx.x;
    {
        int base = bq*8;
        float m = -INFINITY;
        #pragma unroll
        for (int c = 0; c < 8; c++) m = fmaxf(m, g_cm[base + c]);
        float S = 0.f, c0 = 0.f, c1 = 0.f;
        #pragma unroll
        for (int c = 0; c < 8; c++) {
            float e = expf(g_cm[base + c] - m);
            S  += g_cS[base + c] * e;
            c0 += g_cp[(size_t)(base + c)*DK + t] * e;
            c1 += g_cp[(size_t)(base + c)*DK + t + 256] * e;
        }
        cs[t]       = c0 / S;
        cs[t + 256] = c1 / S;
    }
    __syncthreads();
    float pre = bfc[t] + g_seed[(size_t)bq*CC + t];
    #pragma unroll 8
    for (int k2 = 0; k2 < DK; k2++) pre += cs[k2] * Wfc[(size_t)k2*CC + t];
    red[t] = pre;
    __syncthreads();
    for (int o = 128; o; o >>= 1) { if (t < o) red[t] += red[t+o]; __syncthreads(); }
    float mu = red[0] * (1.f/256.f);
    __syncthreads();
    float dd = pre - mu;
    red[t] = dd * dd;
    __syncthreads();
    for (int o = 128; o; o >>= 1) { if (t < o) red[t] += red[t+o]; __syncthreads(); }
    float var = red[0] * (1.f/256.f);
    __syncthreads();
    float prot = dd / sqrtf(var + 1e-5f) * ln_g[t] + ln_b[t];
    ps[t] = prot;
    __syncthreads();
    float pk = 0.f, pq = 0.f;
    #pragma unroll 8
    for (int c = 0; c < CC; c++) {
        float pv = ps[c];
        pk += pv * Wsk[(size_t)c*CC + t];
        pq += pv * Wsq[(size_t)c*CC + t];
    }
    red[t] = pk * pk;
    __syncthreads();
    for (int o = 128; o; o >>= 1) { if (t < o) red[t] += red[t+o]; __syncthreads(); }
    float nk = sqrtf(red[0]);
    __syncthreads();
    red[t] = pq * pq;
    __syncthreads();
    for (int o = 128; o; o >>= 1) { if (t < o) red[t] += red[t+o]; __syncthreads(); }
    float nq2 = sqrtf(red[0]);
    g_pkn[(size_t)bq*CC + t] = pk / fmaxf(nk,  1e-12f);
    g_pqn[(size_t)bq*CC + t] = pq / fmaxf(nq2, 1e-12f);
}

// ---------------------------------------------------------------------------
// rowsim
// ---------------------------------------------------------------------------
__global__ __launch_bounds__(256) void rowsim_kernel(const int* __restrict__ supp_mask)
{
    __shared__ __align__(16) float pkn_s[NQ*CC];
    __shared__ __align__(16) float pqn_s[NQ*CC];
    int t = threadIdx.x, lane = t & 31, wid = t >> 5;
    int g = blockIdx.x * 8 + wid;
    int b = g >> 12;
    for (int i = t; i < NQ*CC; i += 256) {
        pkn_s[i] = g_pkn[(size_t)b*NQ*CC + i];
        pqn_s[i] = g_pqn[(size_t)b*NQ*CC + i];
    }
    __syncthreads();
    const float* qrow = g_qs + (size_t)g*CC;
    const float* krow = g_kk + (size_t)g*CC;
    float4 q0 = *(const float4*)(qrow + lane*4);
    float4 q1 = *(const float4*)(qrow + 128 + lane*4);
    float4 k0 = *(const float4*)(krow + lane*4);
    float4 k1 = *(const float4*)(krow + 128 + lane*4);
    float rnq = 1.f / fmaxf(sqrtf(wsum(d4(q0,q0) + d4(q1,q1))), 1e-12f);
    float rnk = 1.f / fmaxf(sqrtf(wsum(d4(k0,k0) + d4(k1,k1))), 1e-12f);
    float myq2p = 0.f, myK = 0.f;
    float best = -INFINITY; int bk = 0;
    #pragma unroll
    for (int k2 = 0; k2 < NQ; k2++) {
        float4 p0 = *(float4*)&pkn_s[k2*CC + lane*4];
        float4 p1 = *(float4*)&pkn_s[k2*CC + 128 + lane*4];
        float val = wsum(d4(q0,p0) + d4(q1,p1)) * rnq;
        if (val > best) { best = val; bk = k2; }
        if (lane == k2) myq2p = val;
        float4 r0 = *(float4*)&pqn_s[k2*CC + lane*4];
        float4 r1 = *(float4*)&pqn_s[k2*CC + 128 + lane*4];
        float a = wsum(d4(k0,r0) + d4(k1,r1)) * rnk;
        if (lane == k2) myK = expf(20.f * (a - 1.f));
    }
    if (lane < NQ) {
        g_q2p[(size_t)g*NQ + lane]  = myq2p;
        g_Kmat[(size_t)g*NM + lane] = myK;
    }
    if (lane == NQ)
        g_Kmat[(size_t)g*NM + NQ] = (supp_mask[g] > 0) ? expf(-40.f) : 1.f;
    if (lane == 0) g_sidq[g] = bk;
}

// ---------------------------------------------------------------------------
// Sinkhorn: 2-CTA clusters, DSMEM partial exchange
// ---------------------------------------------------------------------------
__global__ __launch_bounds__(512) __cluster_dims__(2,1,1) void sinkhorn_kernel()
{
    __shared__ float sred[16*NM];
    __shared__ float v_s[NM];
    __shared__ float part_s[2][NM];
    int t = threadIdx.x, lane = t & 31, wid = t >> 5;
    int b = blockIdx.x >> 1;
    unsigned rank = blockIdx.x & 1;
    unsigned part_base = (unsigned)__cvta_generic_to_shared(&part_s[0][0]);

    float Kl[4][NM];
    int rowg[4];
    #pragma unroll
    for (int i = 0; i < 4; i++) {
        int n = (int)rank*2048 + i*512 + t;
        rowg[i] = b*NN + n;
        #pragma unroll
        for (int j = 0; j < NM; j++) Kl[i][j] = g_Kmat[(size_t)rowg[i]*NM + j];
    }
    float u[4] = {1.f/NN, 1.f/NN, 1.f/NN, 1.f/NN};

    for (int iter = 0; iter < 100; iter++) {
        #pragma unroll
        for (int j = 0; j < NM; j++) {
            float x = Kl[0][j]*u[0] + Kl[1][j]*u[1] + Kl[2][j]*u[2] + Kl[3][j]*u[3];
            x = wsum(x);
            if (lane == 0) sred[wid*NM + j] = x;
        }
        __syncthreads();
        if (t < NM) {
            float bp = 0.f;
            #pragma unroll
            for (int w2 = 0; w2 < 16; w2++) bp += sred[w2*NM + t];
            part_s[iter & 1][t] = bp;
        }
        asm volatile("barrier.cluster.arrive.aligned;" ::: "memory");
        asm volatile("barrier.cluster.wait.aligned;" ::: "memory");
        if (t < NM) {
            float own  = part_s[iter & 1][t];
            float peer = dsmem_ld_f32(part_base + ((iter & 1)*NM + t)*4u, rank ^ 1u);
            float h0 = rank == 0 ? own : peer;
            float h1 = rank == 0 ? peer : own;
            v_s[t] = g_rowm[b*NM + t] / ((h0 + h1) + 1e-16f);
        }
        __syncthreads();
        #pragma unroll
        for (int i = 0; i < 4; i++) {
            float dsum = 0.f;
            #pragma unroll
            for (int j = 0; j < NM; j++) dsum += Kl[i][j]*v_s[j];
            u[i] = (1.f/NN) / (dsum + 1e-16f);
        }
    }
    asm volatile("barrier.cluster.arrive.aligned;" ::: "memory");
    asm volatile("barrier.cluster.wait.aligned;" ::: "memory");

    #pragma unroll
    for (int i = 0; i < 4; i++) {
        float best = -INFINITY; int bk = 0;
        #pragma unroll
        for (int j = 0; j < NQ; j++) {
            float tv = fmaxf(u[i]*Kl[i][j]*v_s[j]*(float)NN, 0.f);
            g_s2p[(size_t)rowg[i]*NQ + j] = tv;
            if (tv > best) { best = tv; bk = j; }
        }
        g_sids[rowg[i]] = bk;
    }
}

// ---------------------------------------------------------------------------
// kext: build Kext fragments per 32-key tile (frag order, tf32-rounded),
// and fold in the exists-bitmask (atomicOr). Kext cols: [s2p(14) |
// ptab-col(14) | -1e4*valid | 1 | 0 | 0]; col 29 pairs with Qext's -M.
// ---------------------------------------------------------------------------
__global__ __launch_bounds__(256) void kext_kernel(const int* __restrict__ valid)
{
    __shared__ __align__(16) uint2 Ks[512];
    __shared__ unsigned obits[8];
    int kt = blockIdx.x, b = blockIdx.y;
    int t = threadIdx.x, lane = t & 31, w = t >> 5;
    int k0 = kt*32;
    unsigned mybits = 0;
    for (int idx = t; idx < 32*32; idx += 256) {
        int jl = idx >> 5, c = idx & 31;
        int gj = b*NN + k0 + jl;
        float val;
        if (c < 14)       val = g_s2p[(size_t)gj*NQ + c];
        else if (c < 28)  val = g_Ptab[(c - 14)*NQ + g_sids[gj]];
        else if (c == 28) {
            int vv = valid[gj];
            val = -10000.f * (float)vv;
            if (vv == 0) mybits |= g_alignbits[g_sids[gj]];
        }
        else if (c == 29) val = 1.f;
        else              val = 0.f;
        int ks = c >> 3, ck = c & 7;
        int ln = ((jl & 7) << 2) | (ck & 3);
        ((unsigned*)&Ks[((jl >> 3)*4 + ks)*32 + ln])[ck >> 2] = tf32r(val);
    }
    #pragma unroll
    for (int o = 16; o; o >>= 1) mybits |= __shfl_xor_sync(0xffffffffu, mybits, o);
    if (lane == 0) obits[w] = mybits;
    __syncthreads();
    if (t == 0) {
        unsigned m = 0;
        #pragma unroll
        for (int i = 0; i < 8; i++) m |= obits[i];
        if (m) atomicOr(&g_maskbits[b], m);
    }
    uint2* out = g_kextf + ((size_t)(b*128 + kt))*512;
    *(uint4*)(out + 2*t) = *(const uint4*)(&Ks[2*t]);
}

// ---------------------------------------------------------------------------
// Flash v3: K fill = prefetched flat uint4 copy; row offset -M folded into
// Qext col 29 (exp without subtract); fixed-max softmax; swizzled frag V.
// ---------------------------------------------------------------------------
__global__ __launch_bounds__(256, 2) void flash_mma()
{
    __shared__ uint4 Qf[8*4*32];
    __shared__ uint2 Kf[4*4*32];
    __shared__ uint2 Vf[4*16*32];

    const int t = threadIdx.x, lane = t & 31, w = t >> 5;
    const int b = blockIdx.y;
    const int i0 = (blockIdx.x >> 1) * 128;
    const int cbase = (blockIdx.x & 1) * 128;
    const unsigned bits = g_maskbits[b];

    for (int idx = t; idx < 128*32; idx += 256) {
        int q = idx >> 5, c = idx & 31;
        int gi = b*NN + i0 + q;
        float val;
        if (c < 14)       val = g_q2p[(size_t)gi*NQ + c];
        else if (c < 28)  val = (g_sidq[gi] == c - 14) ? 1.f : 0.f;
        else if (c == 28) val = 1.f;
        else if (c == 29) val = ((bits >> g_sidq[gi]) & 1u) ? -1.f : 9999.f;  // -M
        else              val = 0.f;
        int ww = q >> 4, qr = q & 15, ks = c >> 3, ck = c & 7;
        int ln = ((qr & 7) << 2) | (ck & 3);
        int rg = ((ck >> 2) << 1) | (qr >> 3);
        ((unsigned*)&Qf[(ww*4 + ks)*32 + ln])[rg] = tf32r(val);
    }
    __syncthreads();
    uint4 aS[4];
    #pragma unroll
    for (int ks = 0; ks < 4; ks++) aS[ks] = Qf[(w*4 + ks)*32 + lane];

    const int row_lo = i0 + w*16 + (lane >> 2);

    float acc[16][4];
    #pragma unroll
    for (int nb = 0; nb < 16; nb++) {
        acc[nb][0] = 0.f; acc[nb][1] = 0.f; acc[nb][2] = 0.f; acc[nb][3] = 0.f;
    }
    float l_lo = 0.f, l_hi = 0.f;

    const uint4* kxt = ((const uint4*)g_kextf) + (size_t)b*128*256;
    uint4 kreg = kxt[t];                       // prefetch tile 0

    for (int kt = 0; kt < NN/32; kt++) {
        int k0 = kt * 32;
        __syncthreads();
        ((uint4*)Kf)[t] = kreg;
        // V fragments, swizzled frag-major
        #pragma unroll
        for (int i = 0; i < 4; i++) {
            int kr = w + 8*i;
            float4 v4 = *(const float4*)(g_vv + ((size_t)(b*NN + k0 + kr))*CC + cbase + lane*4);
            int kb = kr >> 3, reg = (kr >> 2) & 1, krow = kr & 3;
            float vals[4] = {v4.x, v4.y, v4.z, v4.w};
            #pragma unroll
            for (int e = 0; e < 4; e++) {
                int n  = lane*4 + e;
                int nb = n >> 3, nw = n & 7;
                int ln = ((nw << 2) | krow) ^ VSWZ(nb);
                ((unsigned*)&Vf[(kb*16 + nb)*32 + ln])[reg] = tf32r(vals[e]);
            }
        }
        if (kt + 1 < NN/32) kreg = kxt[(kt + 1)*256 + t];  // prefetch next K tile
        __syncthreads();

        // S = Qext . Kext^T  (includes masks and -M)
        float s0[4], s1[4], s2[4], s3[4];
        #pragma unroll
        for (int nb = 0; nb < 4; nb++) {
            float c0 = 0.f, c1 = 0.f, c2 = 0.f, c3 = 0.f;
            #pragma unroll
            for (int ks = 0; ks < 4; ks++) {
                uint2 bv = Kf[(nb*4 + ks)*32 + lane];
                mma8(c0, c1, c2, c3, aS[ks].x, aS[ks].y, aS[ks].z, aS[ks].w, bv.x, bv.y);
            }
            s0[nb] = c0; s1[nb] = c1; s2[nb] = c2; s3[nb] = c3;
        }

        // p = exp(s) directly (offset already inside s)
        #pragma unroll
        for (int nb = 0; nb < 4; nb++) {
            s0[nb] = __expf(s0[nb]);
            s1[nb] = __expf(s1[nb]);
            s2[nb] = __expf(s2[nb]);
            s3[nb] = __expf(s3[nb]);
            l_lo += s0[nb] + s1[nb];
            l_hi += s2[nb] + s3[nb];
        }

        // P (C-frag) -> A-frags
        const int src0 = (lane & ~3) | ((lane & 3) >> 1);
        const int src2 = src0 + 2;
        const bool odd = lane & 1;
        unsigned pa[4][4];
        #pragma unroll
        for (int kb = 0; kb < 4; kb++) {
            unsigned p0 = tf32r(s0[kb]), p1 = tf32r(s1[kb]);
            unsigned p2 = tf32r(s2[kb]), p3 = tf32r(s3[kb]);
            unsigned q00 = __shfl_sync(0xffffffffu, p0, src0);
            unsigned q01 = __shfl_sync(0xffffffffu, p1, src0);
            unsigned q20 = __shfl_sync(0xffffffffu, p0, src2);
            unsigned q21 = __shfl_sync(0xffffffffu, p1, src2);
            unsigned q10 = __shfl_sync(0xffffffffu, p2, src0);
            unsigned q11 = __shfl_sync(0xffffffffu, p3, src0);
            unsigned q30 = __shfl_sync(0xffffffffu, p2, src2);
            unsigned q31 = __shfl_sync(0xffffffffu, p3, src2);
            pa[kb][0] = odd ? q01 : q00;
            pa[kb][1] = odd ? q11 : q10;
            pa[kb][2] = odd ? q21 : q20;
            pa[kb][3] = odd ? q31 : q30;
        }
        #pragma unroll
        for (int nb = 0; nb < 16; nb++) {
            const uint2* vx = &Vf[nb*32 + (lane ^ VSWZ(nb))];
            #pragma unroll
            for (int kb = 0; kb < 4; kb++) {
                uint2 bv = vx[kb*16*32];
                mma8(acc[nb][0], acc[nb][1], acc[nb][2], acc[nb][3],
                     pa[kb][0], pa[kb][1], pa[kb][2], pa[kb][3], bv.x, bv.y);
            }
        }
    }

    l_lo += __shfl_xor_sync(0xffffffffu, l_lo, 1);
    l_lo += __shfl_xor_sync(0xffffffffu, l_lo, 2);
    l_hi += __shfl_xor_sync(0xffffffffu, l_hi, 1);
    l_hi += __shfl_xor_sync(0xffffffffu, l_hi, 2);
    float il_lo = 1.f / l_lo, il_hi = 1.f / l_hi;
    int col0 = cbase + 2*(lane & 3);
    float* out_lo = g_xattn + ((size_t)b*NN + row_lo)*CC + col0;
    float* out_hi = out_lo + 8*CC;
    #pragma unroll
    for (int nb = 0; nb < 16; nb++) {
        *(float2*)(out_lo + nb*8) = make_float2(acc[nb][0]*il_lo, acc[nb][1]*il_lo);
        *(float2*)(out_hi + nb*8) = make_float2(acc[nb][2]*il_hi, acc[nb][3]*il_hi);
    }
}

// ---------------------------------------------------------------------------
// Launch
// ---------------------------------------------------------------------------
extern "C" void kernel_launch(void* const* d_in, const int* in_sizes, int n_in,
                              void* d_out, int out_size)
{
    (void)in_sizes; (void)n_in; (void)out_size;
    const float* q      = (const float*)d_in[0];
    const float* k      = (const float*)d_in[1];
    const float* v      = (const float*)d_in[2];
    const float* sv     = (const float*)d_in[3];
    const int*   svalid = (const int*)d_in[4];
    const int*   smask  = (const int*)d_in[5];
    const float* Wq     = (const float*)d_in[6];
    const float* Wk     = (const float*)d_in[7];
    const float* Wv     = (const float*)d_in[8];
    const float* Ws     = (const float*)d_in[9];
    const float* Wsq    = (const float*)d_in[10];
    const float* Wsk    = (const float*)d_in[11];
    const float* Wproj  = (const float*)d_in[12];
    const float* Wqs    = (const float*)d_in[13];
    const float* Wks    = (const float*)d_in[14];
    const float* Wvs    = (const float*)d_in[15];
    const float* Wfc    = (const float*)d_in[16];
    const float* bfc    = (const float*)d_in[17];
    const float* lng    = (const float*)d_in[18];
    const float* lnb    = (const float*)d_in[19];
    float* out = (float*)d_out;

    float *p_qs, *p_kk, *p_vv, *p_kh, *p_vh, *p_xa;
    cudaGetSymbolAddress((void**)&p_qs, g_qs);
    cudaGetSymbolAddress((void**)&p_kk, g_kk);
    cudaGetSymbolAddress((void**)&p_vv, g_vv);
    cudaGetSymbolAddress((void**)&p_kh, g_kh);
    cudaGetSymbolAddress((void**)&p_vh, g_vh);
    cudaGetSymbolAddress((void**)&p_xa, g_xattn);

    prep_kernel<<<1, 256>>>(smask);
    gemm_3x_x2<<<dim3(2, 128, 2), 256>>>(q, Wq, p_qs, k, Wk, p_kk);
    gemm_tf32_one<<<dim3(2, 128), 256>>>(v, Wv, p_vv, 256);
    seed_qh_kernel<<<BB*NQ, 1024>>>(sv, Ws, Wqs);
    gemm_tf32_x2<<<dim3(4, 128, 2), 256>>>(p_kk, Wks, p_kh, p_vv, Wvs, p_vh, 512);
    logits_kernel<<<dim3(NN/128, BB), 128>>>(smask);
    ctx_part_kernel<<<dim3(NQ, BB, 8), 512>>>();
    proto_kernel<<<BB*NQ, 256>>>(Wfc, bfc, lng, lnb, Wsk, Wsq);
    rowsim_kernel<<<BB*NN/8, 256>>>(smask);
    sinkhorn_kernel<<<8, 512>>>();
    kext_kernel<<<dim3(128, BB), 256>>>(svalid);
    flash_mma<<<dim3(64, BB), 256>>>();
    gemm_tf32_one<<<dim3(2, 128), 256>>>(p_xa, Wproj, out, 256);
}